// round 6
// baseline (speedup 1.0000x reference)
#include <cuda_runtime.h>
#include <math.h>

// Problem dims (hardcoded per reference): B=4, H=64, W=128, D=128, NS=2
#define D 128
#define LWIN 2048
#define NWIN 16
#define NTOK 32768

// ------------------------- scratch (static device memory) -------------------------
__device__ float g_q[NWIN * LWIN * D];                 // windowed q   (16 MB)
__device__ float g_k[NWIN * LWIN * D];                 // windowed k
__device__ float g_v[NWIN * LWIN * D];                 // windowed v
__device__ float g_ao[NWIN * LWIN * D];                // windowed attn out
__device__ float g_msg[NTOK * D];                      // LN(attn@Wm) in original order
__device__ float g_s[(size_t)NWIN * LWIN * LWIN];      // scores / probs (268 MB)

// ------------------------- index maps (roll + window partition fused) --------------
// windowed (w, l) -> original token row
__device__ __forceinline__ int win_to_src(int w, int l) {
    int b = w >> 2, wi = w & 3;
    int i = wi >> 1, j = wi & 1;
    int y = l >> 6, x = l & 63;            // hh=32, ww=64
    int ys = i * 32 + y, xs = j * 64 + x;  // shifted coords
    int yo = (ys + 16) & 63, xo = (xs + 32) & 127;   // undo roll(-16,-32)
    return (b << 13) + (yo << 7) + xo;
}
// original token row -> windowed flat index (w*LWIN + l)
__device__ __forceinline__ int src_to_win(int r) {
    int b = r >> 13, yo = (r >> 7) & 63, xo = r & 127;
    int ym = (yo + 48) & 63, xm = (xo + 96) & 127;   // (yo-16) mod 64, (xo-32) mod 128
    int i = ym >> 5, y = ym & 31;
    int j = xm >> 6, x = xm & 63;
    int w = (b << 2) + (i << 1) + j;
    int l = (y << 6) + x;
    return w * LWIN + l;
}

// ------------------------- GEMM micro-kernel helpers -------------------------
__device__ __forceinline__ void fma88(const float a[8], const float b[8], float acc[8][8]) {
#pragma unroll
    for (int i = 0; i < 8; i++)
#pragma unroll
        for (int j = 0; j < 8; j++)
            acc[i][j] = fmaf(a[i], b[j], acc[i][j]);
}

// inner product step on k-major staged tiles As[8][128], Bs[8][128]
__device__ __forceinline__ void mm_step_T(const float* __restrict__ As,
                                          const float* __restrict__ Bs,
                                          float acc[8][8], int ty8, int tx8) {
#pragma unroll
    for (int kk = 0; kk < 8; kk++) {
        float4 a0 = *(const float4*)(As + kk * 128 + ty8);
        float4 a1 = *(const float4*)(As + kk * 128 + ty8 + 4);
        float4 b0 = *(const float4*)(Bs + kk * 128 + tx8);
        float4 b1 = *(const float4*)(Bs + kk * 128 + tx8 + 4);
        float a[8] = {a0.x, a0.y, a0.z, a0.w, a1.x, a1.y, a1.z, a1.w};
        float b[8] = {b0.x, b0.y, b0.z, b0.w, b1.x, b1.y, b1.z, b1.w};
        fma88(a, b, acc);
    }
}

// stage 128 rows x 8 cols of row-major src (leading dim ld) transposed -> dst[kk][m]
__device__ __forceinline__ void stageT(float* dst, const float* __restrict__ src,
                                       int ld, int k0, int tid) {
    int m = tid >> 1;
    int kg = (tid & 1) << 2;
    float4 v = *(const float4*)(src + (size_t)m * ld + k0 + kg);
    dst[(kg + 0) * 128 + m] = v.x;
    dst[(kg + 1) * 128 + m] = v.y;
    dst[(kg + 2) * 128 + m] = v.z;
    dst[(kg + 3) * 128 + m] = v.w;
}
__device__ __forceinline__ void stageT_gather(float* dst, const float* __restrict__ src,
                                              const int* __restrict__ rowmap, int k0, int tid) {
    int m = tid >> 1;
    int kg = (tid & 1) << 2;
    float4 v = *(const float4*)(src + (size_t)rowmap[m] * D + k0 + kg);
    dst[(kg + 0) * 128 + m] = v.x;
    dst[(kg + 1) * 128 + m] = v.y;
    dst[(kg + 2) * 128 + m] = v.z;
    dst[(kg + 3) * 128 + m] = v.w;
}
// stage k-major rows directly: dst[kk][n] = src[(k0+kk)*ld + n], n in [0,128)
__device__ __forceinline__ void stageK(float* dst, const float* __restrict__ src,
                                       int ld, int k0, int tid) {
    int kk = tid >> 5;
    int n = (tid & 31) << 2;
    *(float4*)(dst + kk * 128 + n) = *(const float4*)(src + (size_t)(k0 + kk) * ld + n);
}

// ------------------------- K1: QKV projection into windowed layout -------------------------
__global__ void __launch_bounds__(256) k_qkv(const float* __restrict__ src,
                                             const float* __restrict__ tgt,
                                             const float* __restrict__ Wq,
                                             const float* __restrict__ Wk,
                                             const float* __restrict__ Wv) {
    __shared__ float As[8 * 128], Bs[8 * 128];
    __shared__ int rowmap[128];
    int tid = threadIdx.x;
    int which = blockIdx.y;
    const float* A = (which == 0) ? src : tgt;
    const float* W = (which == 0) ? Wq : (which == 1 ? Wk : Wv);
    float* out = (which == 0) ? g_q : (which == 1 ? g_k : g_v);
    int t0 = blockIdx.x * 128;
    if (tid < 128) {
        int t = t0 + tid;
        rowmap[tid] = win_to_src(t >> 11, t & 2047);
    }
    __syncthreads();
    float acc[8][8] = {};
    int ty8 = (tid >> 4) << 3, tx8 = (tid & 15) << 3;
    for (int k0 = 0; k0 < 128; k0 += 8) {
        stageT_gather(As, A, rowmap, k0, tid);
        stageK(Bs, W, 128, k0, tid);
        __syncthreads();
        mm_step_T(As, Bs, acc, ty8, tx8);
        __syncthreads();
    }
#pragma unroll
    for (int i = 0; i < 8; i++) {
        float* p = out + (size_t)(t0 + ty8 + i) * D + tx8;
        *(float4*)p = make_float4(acc[i][0], acc[i][1], acc[i][2], acc[i][3]);
        *(float4*)(p + 4) = make_float4(acc[i][4], acc[i][5], acc[i][6], acc[i][7]);
    }
}

// ------------------------- K2: S = QK^T * scale + mask -------------------------
__global__ void __launch_bounds__(256) k_scores(const float* __restrict__ mask) {
    __shared__ float As[8 * 128], Bs[8 * 128];
    int tid = threadIdx.x;
    int m0 = blockIdx.x * 128, n0 = blockIdx.y * 128, w = blockIdx.z;
    const float* Q = g_q + (size_t)w * LWIN * D + (size_t)m0 * D;
    const float* Kp = g_k + (size_t)w * LWIN * D + (size_t)n0 * D;
    float acc[8][8] = {};
    int ty8 = (tid >> 4) << 3, tx8 = (tid & 15) << 3;
    for (int k0 = 0; k0 < 128; k0 += 8) {
        stageT(As, Q, D, k0, tid);
        stageT(Bs, Kp, D, k0, tid);
        __syncthreads();
        mm_step_T(As, Bs, acc, ty8, tx8);
        __syncthreads();
    }
    const float scale = 0.08838834764831845f;  // 1/sqrt(128)
    int wi = w & 3;
    float* Srow = g_s + (size_t)w * LWIN * LWIN;
    const float* Mrow = mask + (size_t)wi * LWIN * LWIN;
#pragma unroll
    for (int i = 0; i < 8; i++) {
        size_t roff = (size_t)(m0 + ty8 + i) * LWIN + n0 + tx8;
        float4 mk0 = *(const float4*)(Mrow + roff);
        float4 mk1 = *(const float4*)(Mrow + roff + 4);
        float4 o0 = make_float4(fmaf(acc[i][0], scale, mk0.x), fmaf(acc[i][1], scale, mk0.y),
                                fmaf(acc[i][2], scale, mk0.z), fmaf(acc[i][3], scale, mk0.w));
        float4 o1 = make_float4(fmaf(acc[i][4], scale, mk1.x), fmaf(acc[i][5], scale, mk1.y),
                                fmaf(acc[i][6], scale, mk1.z), fmaf(acc[i][7], scale, mk1.w));
        *(float4*)(Srow + roff) = o0;
        *(float4*)(Srow + roff + 4) = o1;
    }
}

// ------------------------- K3: row softmax over 2048 -------------------------
__global__ void __launch_bounds__(256) k_softmax() {
    int tid = threadIdx.x;
    float* row = g_s + (size_t)blockIdx.x * LWIN;
    float4 u0 = *(const float4*)(row + tid * 8);
    float4 u1 = *(const float4*)(row + tid * 8 + 4);
    float v[8] = {u0.x, u0.y, u0.z, u0.w, u1.x, u1.y, u1.z, u1.w};
    float mx = v[0];
#pragma unroll
    for (int i = 1; i < 8; i++) mx = fmaxf(mx, v[i]);
    __shared__ float red[8];
#pragma unroll
    for (int off = 16; off; off >>= 1) mx = fmaxf(mx, __shfl_xor_sync(0xffffffffu, mx, off));
    if ((tid & 31) == 0) red[tid >> 5] = mx;
    __syncthreads();
    float bm = red[0];
#pragma unroll
    for (int i = 1; i < 8; i++) bm = fmaxf(bm, red[i]);
    float s = 0.f;
#pragma unroll
    for (int i = 0; i < 8; i++) { v[i] = expf(v[i] - bm); s += v[i]; }
    __syncthreads();
#pragma unroll
    for (int off = 16; off; off >>= 1) s += __shfl_xor_sync(0xffffffffu, s, off);
    if ((tid & 31) == 0) red[tid >> 5] = s;
    __syncthreads();
    float tot = 0.f;
#pragma unroll
    for (int i = 0; i < 8; i++) tot += red[i];
    float inv = 1.0f / tot;
#pragma unroll
    for (int i = 0; i < 8; i++) v[i] *= inv;
    *(float4*)(row + tid * 8) = make_float4(v[0], v[1], v[2], v[3]);
    *(float4*)(row + tid * 8 + 4) = make_float4(v[4], v[5], v[6], v[7]);
}

// ------------------------- K4: O = P @ V -------------------------
__global__ void __launch_bounds__(256) k_pv() {
    __shared__ float As[8 * 128], Bs[8 * 128];
    int tid = threadIdx.x;
    int m0 = blockIdx.x * 128, w = blockIdx.y;
    const float* P = g_s + (size_t)w * LWIN * LWIN + (size_t)m0 * LWIN;
    const float* V = g_v + (size_t)w * LWIN * D;
    float acc[8][8] = {};
    int ty8 = (tid >> 4) << 3, tx8 = (tid & 15) << 3;
    for (int k0 = 0; k0 < LWIN; k0 += 8) {
        stageT(As, P, LWIN, k0, tid);
        stageK(Bs, V, D, k0, tid);
        __syncthreads();
        mm_step_T(As, Bs, acc, ty8, tx8);
        __syncthreads();
    }
#pragma unroll
    for (int i = 0; i < 8; i++) {
        float* p = g_ao + (size_t)(w * LWIN + m0 + ty8 + i) * D + tx8;
        *(float4*)p = make_float4(acc[i][0], acc[i][1], acc[i][2], acc[i][3]);
        *(float4*)(p + 4) = make_float4(acc[i][4], acc[i][5], acc[i][6], acc[i][7]);
    }
}

// ------------------------- K5: msg = LN((window-merged O) @ Wm) -------------------------
__global__ void __launch_bounds__(256) k_msg(const float* __restrict__ Wm,
                                             const float* __restrict__ g1,
                                             const float* __restrict__ b1) {
    __shared__ float As[8 * 128], Bs[8 * 128];
    __shared__ int rowmap[128];
    int tid = threadIdx.x;
    int r0 = blockIdx.x * 128;
    if (tid < 128) rowmap[tid] = src_to_win(r0 + tid);  // windowed flat index
    __syncthreads();
    float acc[8][8] = {};
    int ty8 = (tid >> 4) << 3, tx8 = (tid & 15) << 3;
    for (int k0 = 0; k0 < 128; k0 += 8) {
        stageT_gather(As, g_ao, rowmap, k0, tid);
        stageK(Bs, Wm, 128, k0, tid);
        __syncthreads();
        mm_step_T(As, Bs, acc, ty8, tx8);
        __syncthreads();
    }
    float gv[8], bv[8];
#pragma unroll
    for (int j = 0; j < 8; j++) { gv[j] = g1[tx8 + j]; bv[j] = b1[tx8 + j]; }
#pragma unroll
    for (int i = 0; i < 8; i++) {
        float s1 = 0.f, s2 = 0.f;
#pragma unroll
        for (int j = 0; j < 8; j++) { s1 += acc[i][j]; s2 += acc[i][j] * acc[i][j]; }
#pragma unroll
        for (int off = 8; off; off >>= 1) {
            s1 += __shfl_xor_sync(0xffffffffu, s1, off, 16);
            s2 += __shfl_xor_sync(0xffffffffu, s2, off, 16);
        }
        float mean = s1 * (1.0f / 128.0f);
        float var = s2 * (1.0f / 128.0f) - mean * mean;
        float rstd = rsqrtf(var + 1e-5f);
        float o[8];
#pragma unroll
        for (int j = 0; j < 8; j++) o[j] = (acc[i][j] - mean) * rstd * gv[j] + bv[j];
        float* p = g_msg + (size_t)(r0 + ty8 + i) * D + tx8;
        *(float4*)p = make_float4(o[0], o[1], o[2], o[3]);
        *(float4*)(p + 4) = make_float4(o[4], o[5], o[6], o[7]);
    }
}

// ------------------------- K6: fused concat-MLP + LN + residual -------------------------
#define LDA 260
#define LDH 132
__global__ void __launch_bounds__(256, 1) k_mlp(const float* __restrict__ src,
                                                const float* __restrict__ W1,
                                                const float* __restrict__ W2,
                                                const float* __restrict__ g2,
                                                const float* __restrict__ b2,
                                                float* __restrict__ out) {
    extern __shared__ float sm[];
    float* Asr = sm;                  // [128][LDA] concat(src,msg) rows
    float* Hs = sm + 128 * LDA;       // [128][LDH] gelu'd hidden chunk
    float* Bs = Hs + 128 * LDH;       // [8][128]
    int tid = threadIdx.x;
    int r0 = blockIdx.x * 128;
    // stage concat rows: cols 0..127 = src, 128..255 = g_msg
    for (int e = tid; e < 128 * 64; e += 256) {
        int m = e >> 6, c4 = e & 63;
        float4 v;
        if (c4 < 32) v = *(const float4*)(src + (size_t)(r0 + m) * D + c4 * 4);
        else v = *(const float4*)(g_msg + (size_t)(r0 + m) * D + (c4 - 32) * 4);
        *(float4*)(Asr + m * LDA + c4 * 4) = v;
    }
    __syncthreads();
    int ty8 = (tid >> 4) << 3, tx8 = (tid & 15) << 3;
    float acc2[8][8] = {};
    for (int c = 0; c < 8; c++) {  // hidden chunks of 128
        float acc1[8][8] = {};
        for (int k0 = 0; k0 < 256; k0 += 8) {
            stageK(Bs, W1 + c * 128, 1024, k0, tid);
            __syncthreads();
#pragma unroll
            for (int kk = 0; kk < 8; kk++) {
                float4 b0 = *(const float4*)(Bs + kk * 128 + tx8);
                float4 b1f = *(const float4*)(Bs + kk * 128 + tx8 + 4);
                float b[8] = {b0.x, b0.y, b0.z, b0.w, b1f.x, b1f.y, b1f.z, b1f.w};
                float a[8];
#pragma unroll
                for (int i = 0; i < 8; i++) a[i] = Asr[(ty8 + i) * LDA + k0 + kk];
                fma88(a, b, acc1);
            }
            __syncthreads();
        }
        // GELU (exact, erf) -> Hs row-major
#pragma unroll
        for (int i = 0; i < 8; i++) {
            float h[8];
#pragma unroll
            for (int j = 0; j < 8; j++) {
                float x = acc1[i][j];
                h[j] = 0.5f * x * (1.0f + erff(x * 0.70710678118654752f));
            }
            *(float4*)(Hs + (ty8 + i) * LDH + tx8) = make_float4(h[0], h[1], h[2], h[3]);
            *(float4*)(Hs + (ty8 + i) * LDH + tx8 + 4) = make_float4(h[4], h[5], h[6], h[7]);
        }
        __syncthreads();
        // acc2 += Hs @ W2[c*128 : (c+1)*128, :]
        for (int k0 = 0; k0 < 128; k0 += 8) {
            stageK(Bs, W2, 128, c * 128 + k0, tid);
            __syncthreads();
#pragma unroll
            for (int kk = 0; kk < 8; kk++) {
                float4 b0 = *(const float4*)(Bs + kk * 128 + tx8);
                float4 b1f = *(const float4*)(Bs + kk * 128 + tx8 + 4);
                float b[8] = {b0.x, b0.y, b0.z, b0.w, b1f.x, b1f.y, b1f.z, b1f.w};
                float a[8];
#pragma unroll
                for (int i = 0; i < 8; i++) a[i] = Hs[(ty8 + i) * LDH + k0 + kk];
                fma88(a, b, acc2);
            }
            __syncthreads();
        }
    }
    // LN + residual
    float gv[8], bv[8];
#pragma unroll
    for (int j = 0; j < 8; j++) { gv[j] = g2[tx8 + j]; bv[j] = b2[tx8 + j]; }
#pragma unroll
    for (int i = 0; i < 8; i++) {
        float s1 = 0.f, s2 = 0.f;
#pragma unroll
        for (int j = 0; j < 8; j++) { s1 += acc2[i][j]; s2 += acc2[i][j] * acc2[i][j]; }
#pragma unroll
        for (int off = 8; off; off >>= 1) {
            s1 += __shfl_xor_sync(0xffffffffu, s1, off, 16);
            s2 += __shfl_xor_sync(0xffffffffu, s2, off, 16);
        }
        float mean = s1 * (1.0f / 128.0f);
        float var = s2 * (1.0f / 128.0f) - mean * mean;
        float rstd = rsqrtf(var + 1e-5f);
        int m = ty8 + i;
        float o[8];
#pragma unroll
        for (int j = 0; j < 8; j++) {
            float y = (acc2[i][j] - mean) * rstd * gv[j] + bv[j];
            o[j] = y + Asr[m * LDA + tx8 + j];   // residual from staged src
        }
        float* p = out + (size_t)(r0 + m) * D + tx8;
        *(float4*)p = make_float4(o[0], o[1], o[2], o[3]);
        *(float4*)(p + 4) = make_float4(o[4], o[5], o[6], o[7]);
    }
}

// ------------------------- launch -------------------------
extern "C" void kernel_launch(void* const* d_in, const int* in_sizes, int n_in,
                              void* d_out, int out_size) {
    (void)in_sizes; (void)n_in; (void)out_size;
    const float* src  = (const float*)d_in[0];
    const float* tgt  = (const float*)d_in[1];
    const float* mask = (const float*)d_in[2];
    const float* Wq   = (const float*)d_in[8];
    const float* Wk   = (const float*)d_in[9];
    const float* Wv   = (const float*)d_in[10];
    const float* Wm   = (const float*)d_in[11];
    const float* g1   = (const float*)d_in[12];
    const float* b1   = (const float*)d_in[13];
    const float* W1   = (const float*)d_in[14];
    const float* W2   = (const float*)d_in[15];
    const float* g2   = (const float*)d_in[16];
    const float* b2   = (const float*)d_in[17];
    float* out = (float*)d_out;

    k_qkv<<<dim3(256, 3), 256>>>(src, tgt, Wq, Wk, Wv);
    k_scores<<<dim3(16, 16, 16), 256>>>(mask);
    k_softmax<<<NWIN * LWIN, 256>>>();
    k_pv<<<dim3(16, 16), 256>>>();
    k_msg<<<256, 256>>>(Wm, g1, b1);
    const int smemMLP = (128 * LDA + 128 * LDH + 8 * 128) * 4;
    cudaFuncSetAttribute(k_mlp, cudaFuncAttributeMaxDynamicSharedMemorySize, smemMLP);
    k_mlp<<<256, 256, smemMLP>>>(src, W1, W2, g2, b2, out);
}

// round 10
// speedup vs baseline: 2.1017x; 2.1017x over previous
#include <cuda_runtime.h>
#include <math.h>

// Problem dims (hardcoded per reference): B=4, H=64, W=128, D=128, NS=2
#define D 128
#define LWIN 2048
#define NWIN 16
#define NTOK 32768
#define LDT 132   // padded leading dim for staged smem tiles (kills bank conflicts)

// ------------------------- scratch (static device memory) -------------------------
__device__ float g_q[NWIN * LWIN * D];                 // windowed q (tf32-rounded fp32)
__device__ float g_k[NWIN * LWIN * D];                 // windowed k (tf32-rounded)
__device__ float g_v[NWIN * LWIN * D];                 // windowed v (tf32-rounded)
__device__ float g_ao[NWIN * LWIN * D];                // windowed attn out (fp32)
__device__ float g_msg[NTOK * D];                      // LN(attn@Wm) original order (fp32)
__device__ float g_h[(size_t)NTOK * 1024];             // gelu hidden (tf32-rounded) 134MB
__device__ float g_s[(size_t)NWIN * LWIN * LWIN];      // scores / probs (268 MB)

// ------------------------- index maps (roll + window partition fused) --------------
__device__ __forceinline__ int win_to_src(int w, int l) {
    int b = w >> 2, wi = w & 3;
    int i = wi >> 1, j = wi & 1;
    int y = l >> 6, x = l & 63;            // hh=32, ww=64
    int ys = i * 32 + y, xs = j * 64 + x;
    int yo = (ys + 16) & 63, xo = (xs + 32) & 127;
    return (b << 13) + (yo << 7) + xo;
}
__device__ __forceinline__ int src_to_win(int r) {
    int b = r >> 13, yo = (r >> 7) & 63, xo = r & 127;
    int ym = (yo + 48) & 63, xm = (xo + 96) & 127;
    int i = ym >> 5, y = ym & 31;
    int j = xm >> 6, x = xm & 63;
    int w = (b << 2) + (i << 1) + j;
    int l = (y << 6) + x;
    return w * LWIN + l;
}

// ------------------------- tf32 helpers -------------------------
__device__ __forceinline__ unsigned f2tf(float x) {
    unsigned r; asm("cvt.rna.tf32.f32 %0, %1;" : "=r"(r) : "f"(x)); return r;
}
__device__ __forceinline__ float tf32r(float x) { return __uint_as_float(f2tf(x)); }

__device__ __forceinline__ void mma8(float* c, const unsigned* a, const unsigned* b) {
    asm volatile("mma.sync.aligned.m16n8k8.row.col.f32.tf32.tf32.f32 "
                 "{%0,%1,%2,%3}, {%4,%5,%6,%7}, {%8,%9}, {%0,%1,%2,%3};\n"
                 : "+f"(c[0]), "+f"(c[1]), "+f"(c[2]), "+f"(c[3])
                 : "r"(a[0]), "r"(a[1]), "r"(a[2]), "r"(a[3]), "r"(b[0]), "r"(b[1]));
}

// ------------------------- staging -------------------------
// transpose-stage 128 rows x 16 k of row-major src -> dst[k][m] (LDT-padded)
template <bool CVT>
__device__ __forceinline__ void stT(float* dst, const float* __restrict__ src,
                                    size_t ld, int k0, int tid) {
    int m = tid >> 1, ks = (tid & 1) * 8;
    const float* p = src + (size_t)m * ld + k0 + ks;
    float4 v0 = *(const float4*)p, v1 = *(const float4*)(p + 4);
    float vv[8] = {v0.x, v0.y, v0.z, v0.w, v1.x, v1.y, v1.z, v1.w};
#pragma unroll
    for (int j = 0; j < 8; j++)
        dst[(ks + j) * LDT + m] = CVT ? tf32r(vv[j]) : vv[j];
}
// gathered transpose-stage via rowmap (D-wide rows)
template <bool CVT>
__device__ __forceinline__ void stTg(float* dst, const float* __restrict__ src,
                                     const int* __restrict__ rowmap, int k0, int tid) {
    int m = tid >> 1, ks = (tid & 1) * 8;
    const float* p = src + (size_t)rowmap[m] * D + k0 + ks;
    float4 v0 = *(const float4*)p, v1 = *(const float4*)(p + 4);
    float vv[8] = {v0.x, v0.y, v0.z, v0.w, v1.x, v1.y, v1.z, v1.w};
#pragma unroll
    for (int j = 0; j < 8; j++)
        dst[(ks + j) * LDT + m] = CVT ? tf32r(vv[j]) : vv[j];
}
// direct stage of k-major B rows: dst[k][n] = src[(k0+k)*ld + n], n in [0,128)
template <bool CVT>
__device__ __forceinline__ void stK(float* dst, const float* __restrict__ src,
                                    size_t ld, int k0, int tid) {
    int kk = tid >> 4, n = (tid & 15) * 8;
    const float* p = src + (size_t)(k0 + kk) * ld + n;
    float4 v0 = *(const float4*)p, v1 = *(const float4*)(p + 4);
    if (CVT) {
        v0.x = tf32r(v0.x); v0.y = tf32r(v0.y); v0.z = tf32r(v0.z); v0.w = tf32r(v0.w);
        v1.x = tf32r(v1.x); v1.y = tf32r(v1.y); v1.z = tf32r(v1.z); v1.w = tf32r(v1.w);
    }
    *(float4*)(dst + kk * LDT + n) = v0;
    *(float4*)(dst + kk * LDT + n + 4) = v1;
}

// ------------------------- mma compute on one BK=16 stage -------------------------
// warps 4x2 (wy,wx), warp tile 32m x 64n, c[2 mtiles][8 ntiles][4]
__device__ __forceinline__ void mma_stage(const float* As, const float* Bs,
                                          float c[2][8][4], int wy, int wx, int g, int tig) {
#pragma unroll
    for (int k8 = 0; k8 < 16; k8 += 8) {
        unsigned a[2][4], b[8][2];
#pragma unroll
        for (int mt = 0; mt < 2; mt++) {
            int mb = wy * 32 + mt * 16;
            a[mt][0] = __float_as_uint(As[(k8 + tig) * LDT + mb + g]);
            a[mt][1] = __float_as_uint(As[(k8 + tig) * LDT + mb + 8 + g]);
            a[mt][2] = __float_as_uint(As[(k8 + tig + 4) * LDT + mb + g]);
            a[mt][3] = __float_as_uint(As[(k8 + tig + 4) * LDT + mb + 8 + g]);
        }
#pragma unroll
        for (int nt = 0; nt < 8; nt++) {
            int nb = wx * 64 + nt * 8;
            b[nt][0] = __float_as_uint(Bs[(k8 + tig) * LDT + nb + g]);
            b[nt][1] = __float_as_uint(Bs[(k8 + tig + 4) * LDT + nb + g]);
        }
#pragma unroll
        for (int mt = 0; mt < 2; mt++)
#pragma unroll
            for (int nt = 0; nt < 8; nt++) mma8(c[mt][nt], a[mt], b[nt]);
    }
}

// ------------------------- K1: QKV projection (mma, gathered, tf32-rounded out) ------
__global__ void __launch_bounds__(256) k_qkv(const float* __restrict__ src,
                                             const float* __restrict__ tgt,
                                             const float* __restrict__ Wq,
                                             const float* __restrict__ Wk,
                                             const float* __restrict__ Wv) {
    __shared__ float As[16 * LDT], Bs[16 * LDT];
    __shared__ int rowmap[128];
    int tid = threadIdx.x;
    int which = blockIdx.y;
    const float* A = (which == 0) ? src : tgt;
    const float* W = (which == 0) ? Wq : (which == 1 ? Wk : Wv);
    float* out = (which == 0) ? g_q : (which == 1 ? g_k : g_v);
    int t0 = blockIdx.x * 128;
    if (tid < 128) { int t = t0 + tid; rowmap[tid] = win_to_src(t >> 11, t & 2047); }
    __syncthreads();
    int warp = tid >> 5, lane = tid & 31, wy = warp >> 1, wx = warp & 1;
    int g = lane >> 2, tig = lane & 3;
    float c[2][8][4] = {};
    for (int k0 = 0; k0 < 128; k0 += 16) {
        stTg<true>(As, A, rowmap, k0, tid);
        stK<true>(Bs, W, 128, k0, tid);
        __syncthreads();
        mma_stage(As, Bs, c, wy, wx, g, tig);
        __syncthreads();
    }
#pragma unroll
    for (int mt = 0; mt < 2; mt++) {
        int r = t0 + wy * 32 + mt * 16 + g;
#pragma unroll
        for (int nt = 0; nt < 8; nt++) {
            int col = wx * 64 + nt * 8 + 2 * tig;
            *(float2*)(out + (size_t)r * D + col) =
                make_float2(tf32r(c[mt][nt][0]), tf32r(c[mt][nt][1]));
            *(float2*)(out + (size_t)(r + 8) * D + col) =
                make_float2(tf32r(c[mt][nt][2]), tf32r(c[mt][nt][3]));
        }
    }
}

// ------------------------- K2: S = QK^T * scale + mask -------------------------
__global__ void __launch_bounds__(256) k_scores(const float* __restrict__ mask) {
    __shared__ float As[16 * LDT], Bs[16 * LDT];
    int tid = threadIdx.x;
    int m0 = blockIdx.x * 128, n0 = blockIdx.y * 128, w = blockIdx.z;
    const float* Q = g_q + (size_t)w * LWIN * D + (size_t)m0 * D;
    const float* Kp = g_k + (size_t)w * LWIN * D + (size_t)n0 * D;
    int warp = tid >> 5, lane = tid & 31, wy = warp >> 1, wx = warp & 1;
    int g = lane >> 2, tig = lane & 3;
    float c[2][8][4] = {};
    for (int k0 = 0; k0 < 128; k0 += 16) {
        stT<false>(As, Q, D, k0, tid);
        stT<false>(Bs, Kp, D, k0, tid);
        __syncthreads();
        mma_stage(As, Bs, c, wy, wx, g, tig);
        __syncthreads();
    }
    const float scale = 0.08838834764831845f;  // 1/sqrt(128)
    const float* M = mask + (size_t)(w & 3) * LWIN * LWIN;
    float* S = g_s + (size_t)w * LWIN * LWIN;
#pragma unroll
    for (int mt = 0; mt < 2; mt++) {
        int r = m0 + wy * 32 + mt * 16 + g;
#pragma unroll
        for (int nt = 0; nt < 8; nt++) {
            int col = n0 + wx * 64 + nt * 8 + 2 * tig;
            size_t o0 = (size_t)r * LWIN + col, o1 = (size_t)(r + 8) * LWIN + col;
            float2 mk0 = *(const float2*)(M + o0), mk1 = *(const float2*)(M + o1);
            *(float2*)(S + o0) = make_float2(fmaf(c[mt][nt][0], scale, mk0.x),
                                             fmaf(c[mt][nt][1], scale, mk0.y));
            *(float2*)(S + o1) = make_float2(fmaf(c[mt][nt][2], scale, mk1.x),
                                             fmaf(c[mt][nt][3], scale, mk1.y));
        }
    }
}

// ------------------------- K3: row softmax over 2048, output tf32-rounded ------------
__global__ void __launch_bounds__(256) k_softmax() {
    int tid = threadIdx.x;
    float* row = g_s + (size_t)blockIdx.x * LWIN;
    float4 u0 = *(const float4*)(row + tid * 8);
    float4 u1 = *(const float4*)(row + tid * 8 + 4);
    float v[8] = {u0.x, u0.y, u0.z, u0.w, u1.x, u1.y, u1.z, u1.w};
    float mx = v[0];
#pragma unroll
    for (int i = 1; i < 8; i++) mx = fmaxf(mx, v[i]);
    __shared__ float red[8];
#pragma unroll
    for (int off = 16; off; off >>= 1) mx = fmaxf(mx, __shfl_xor_sync(0xffffffffu, mx, off));
    if ((tid & 31) == 0) red[tid >> 5] = mx;
    __syncthreads();
    float bm = red[0];
#pragma unroll
    for (int i = 1; i < 8; i++) bm = fmaxf(bm, red[i]);
    float s = 0.f;
#pragma unroll
    for (int i = 0; i < 8; i++) { v[i] = expf(v[i] - bm); s += v[i]; }
    __syncthreads();
#pragma unroll
    for (int off = 16; off; off >>= 1) s += __shfl_xor_sync(0xffffffffu, s, off);
    if ((tid & 31) == 0) red[tid >> 5] = s;
    __syncthreads();
    float tot = 0.f;
#pragma unroll
    for (int i = 0; i < 8; i++) tot += red[i];
    float inv = 1.0f / tot;
#pragma unroll
    for (int i = 0; i < 8; i++) v[i] = tf32r(v[i] * inv);
    *(float4*)(row + tid * 8) = make_float4(v[0], v[1], v[2], v[3]);
    *(float4*)(row + tid * 8 + 4) = make_float4(v[4], v[5], v[6], v[7]);
}

// ------------------------- K4: O = P @ V -------------------------
__global__ void __launch_bounds__(256) k_pv() {
    __shared__ float As[16 * LDT], Bs[16 * LDT];
    int tid = threadIdx.x;
    int m0 = blockIdx.x * 128, w = blockIdx.y;
    const float* P = g_s + (size_t)w * LWIN * LWIN + (size_t)m0 * LWIN;
    const float* V = g_v + (size_t)w * LWIN * D;
    int warp = tid >> 5, lane = tid & 31, wy = warp >> 1, wx = warp & 1;
    int g = lane >> 2, tig = lane & 3;
    float c[2][8][4] = {};
    for (int k0 = 0; k0 < LWIN; k0 += 16) {
        stT<false>(As, P, LWIN, k0, tid);
        stK<false>(Bs, V, D, k0, tid);
        __syncthreads();
        mma_stage(As, Bs, c, wy, wx, g, tig);
        __syncthreads();
    }
    float* O = g_ao + (size_t)(w * LWIN + m0) * D;
#pragma unroll
    for (int mt = 0; mt < 2; mt++) {
        int r = wy * 32 + mt * 16 + g;
#pragma unroll
        for (int nt = 0; nt < 8; nt++) {
            int col = wx * 64 + nt * 8 + 2 * tig;
            *(float2*)(O + (size_t)r * D + col) = make_float2(c[mt][nt][0], c[mt][nt][1]);
            *(float2*)(O + (size_t)(r + 8) * D + col) = make_float2(c[mt][nt][2], c[mt][nt][3]);
        }
    }
}

// ------------------------- K5: msg = LN((window-merged O) @ Wm) ----------------------
__global__ void __launch_bounds__(256) k_msg(const float* __restrict__ Wm,
                                             const float* __restrict__ g1,
                                             const float* __restrict__ b1) {
    __shared__ float As[16 * LDT], Bs[16 * LDT];
    __shared__ int rowmap[128];
    __shared__ float red1[2 * 128], red2[2 * 128];
    int tid = threadIdx.x;
    int r0 = blockIdx.x * 128;
    if (tid < 128) rowmap[tid] = src_to_win(r0 + tid);
    __syncthreads();
    int warp = tid >> 5, lane = tid & 31, wy = warp >> 1, wx = warp & 1;
    int g = lane >> 2, tig = lane & 3;
    float c[2][8][4] = {};
    for (int k0 = 0; k0 < 128; k0 += 16) {
        stTg<true>(As, g_ao, rowmap, k0, tid);
        stK<true>(Bs, Wm, 128, k0, tid);
        __syncthreads();
        mma_stage(As, Bs, c, wy, wx, g, tig);
        __syncthreads();
    }
    // LN: per-row sums over the 128 output cols
#pragma unroll
    for (int mt = 0; mt < 2; mt++) {
        float sA1 = 0.f, sA2 = 0.f, sB1 = 0.f, sB2 = 0.f;
#pragma unroll
        for (int nt = 0; nt < 8; nt++) {
            sA1 += c[mt][nt][0] + c[mt][nt][1];
            sA2 += c[mt][nt][0] * c[mt][nt][0] + c[mt][nt][1] * c[mt][nt][1];
            sB1 += c[mt][nt][2] + c[mt][nt][3];
            sB2 += c[mt][nt][2] * c[mt][nt][2] + c[mt][nt][3] * c[mt][nt][3];
        }
#pragma unroll
        for (int o = 1; o < 4; o <<= 1) {
            sA1 += __shfl_xor_sync(0xffffffffu, sA1, o);
            sA2 += __shfl_xor_sync(0xffffffffu, sA2, o);
            sB1 += __shfl_xor_sync(0xffffffffu, sB1, o);
            sB2 += __shfl_xor_sync(0xffffffffu, sB2, o);
        }
        if (tig == 0) {
            int rA = wy * 32 + mt * 16 + g, rB = rA + 8;
            red1[wx * 128 + rA] = sA1; red2[wx * 128 + rA] = sA2;
            red1[wx * 128 + rB] = sB1; red2[wx * 128 + rB] = sB2;
        }
    }
    __syncthreads();
#pragma unroll
    for (int mt = 0; mt < 2; mt++) {
        int rA = wy * 32 + mt * 16 + g, rB = rA + 8;
        float mA = (red1[rA] + red1[128 + rA]) * (1.0f / 128.0f);
        float vA = (red2[rA] + red2[128 + rA]) * (1.0f / 128.0f) - mA * mA;
        float rsA = rsqrtf(vA + 1e-5f);
        float mB = (red1[rB] + red1[128 + rB]) * (1.0f / 128.0f);
        float vB = (red2[rB] + red2[128 + rB]) * (1.0f / 128.0f) - mB * mB;
        float rsB = rsqrtf(vB + 1e-5f);
#pragma unroll
        for (int nt = 0; nt < 8; nt++) {
            int col = wx * 64 + nt * 8 + 2 * tig;
            float2 gg = *(const float2*)(g1 + col);
            float2 bb = *(const float2*)(b1 + col);
            *(float2*)(g_msg + (size_t)(r0 + rA) * D + col) =
                make_float2((c[mt][nt][0] - mA) * rsA * gg.x + bb.x,
                            (c[mt][nt][1] - mA) * rsA * gg.y + bb.y);
            *(float2*)(g_msg + (size_t)(r0 + rB) * D + col) =
                make_float2((c[mt][nt][2] - mB) * rsB * gg.x + bb.x,
                            (c[mt][nt][3] - mB) * rsB * gg.y + bb.y);
        }
    }
}

// ------------------------- K6: h = gelu(concat(src,msg) @ W1) ------------------------
__global__ void __launch_bounds__(256) k_h(const float* __restrict__ src,
                                           const float* __restrict__ W1) {
    __shared__ float As[16 * LDT], Bs[16 * LDT];
    int tid = threadIdx.x;
    int r0 = blockIdx.x * 128;
    int nch = blockIdx.y * 128;   // hidden chunk in [0,1024)
    int warp = tid >> 5, lane = tid & 31, wy = warp >> 1, wx = warp & 1;
    int g = lane >> 2, tig = lane & 3;
    float c[2][8][4] = {};
    for (int k0 = 0; k0 < 256; k0 += 16) {
        if (k0 < 128) stT<true>(As, src + (size_t)r0 * D, D, k0, tid);
        else          stT<true>(As, g_msg + (size_t)r0 * D, D, k0 - 128, tid);
        stK<true>(Bs, W1 + nch, 1024, k0, tid);
        __syncthreads();
        mma_stage(As, Bs, c, wy, wx, g, tig);
        __syncthreads();
    }
#pragma unroll
    for (int mt = 0; mt < 2; mt++) {
        int r = r0 + wy * 32 + mt * 16 + g;
#pragma unroll
        for (int nt = 0; nt < 8; nt++) {
            int col = nch + wx * 64 + nt * 8 + 2 * tig;
            float o[4];
#pragma unroll
            for (int j = 0; j < 4; j++) {
                float x = c[mt][nt][j];
                o[j] = tf32r(0.5f * x * (1.0f + erff(x * 0.70710678118654752f)));
            }
            *(float2*)(g_h + (size_t)r * 1024 + col) = make_float2(o[0], o[1]);
            *(float2*)(g_h + (size_t)(r + 8) * 1024 + col) = make_float2(o[2], o[3]);
        }
    }
}

// ------------------------- K7: out = src + LN(h @ W2) -------------------------
__global__ void __launch_bounds__(256) k_out(const float* __restrict__ src,
                                             const float* __restrict__ W2,
                                             const float* __restrict__ g2,
                                             const float* __restrict__ b2,
                                             float* __restrict__ out) {
    __shared__ float As[16 * LDT], Bs[16 * LDT];
    __shared__ float red1[2 * 128], red2[2 * 128];
    int tid = threadIdx.x;
    int r0 = blockIdx.x * 128;
    int warp = tid >> 5, lane = tid & 31, wy = warp >> 1, wx = warp & 1;
    int g = lane >> 2, tig = lane & 3;
    float c[2][8][4] = {};
    for (int k0 = 0; k0 < 1024; k0 += 16) {
        stT<false>(As, g_h + (size_t)r0 * 1024, 1024, k0, tid);
        stK<true>(Bs, W2, 128, k0, tid);
        __syncthreads();
        mma_stage(As, Bs, c, wy, wx, g, tig);
        __syncthreads();
    }
    // LN reduction
#pragma unroll
    for (int mt = 0; mt < 2; mt++) {
        float sA1 = 0.f, sA2 = 0.f, sB1 = 0.f, sB2 = 0.f;
#pragma unroll
        for (int nt = 0; nt < 8; nt++) {
            sA1 += c[mt][nt][0] + c[mt][nt][1];
            sA2 += c[mt][nt][0] * c[mt][nt][0] + c[mt][nt][1] * c[mt][nt][1];
            sB1 += c[mt][nt][2] + c[mt][nt][3];
            sB2 += c[mt][nt][2] * c[mt][nt][2] + c[mt][nt][3] * c[mt][nt][3];
        }
#pragma unroll
        for (int o = 1; o < 4; o <<= 1) {
            sA1 += __shfl_xor_sync(0xffffffffu, sA1, o);
            sA2 += __shfl_xor_sync(0xffffffffu, sA2, o);
            sB1 += __shfl_xor_sync(0xffffffffu, sB1, o);
            sB2 += __shfl_xor_sync(0xffffffffu, sB2, o);
        }
        if (tig == 0) {
            int rA = wy * 32 + mt * 16 + g, rB = rA + 8;
            red1[wx * 128 + rA] = sA1; red2[wx * 128 + rA] = sA2;
            red1[wx * 128 + rB] = sB1; red2[wx * 128 + rB] = sB2;
        }
    }
    __syncthreads();
#pragma unroll
    for (int mt = 0; mt < 2; mt++) {
        int rA = wy * 32 + mt * 16 + g, rB = rA + 8;
        float mA = (red1[rA] + red1[128 + rA]) * (1.0f / 128.0f);
        float vA = (red2[rA] + red2[128 + rA]) * (1.0f / 128.0f) - mA * mA;
        float rsA = rsqrtf(vA + 1e-5f);
        float mB = (red1[rB] + red1[128 + rB]) * (1.0f / 128.0f);
        float vB = (red2[rB] + red2[128 + rB]) * (1.0f / 128.0f) - mB * mB;
        float rsB = rsqrtf(vB + 1e-5f);
#pragma unroll
        for (int nt = 0; nt < 8; nt++) {
            int col = wx * 64 + nt * 8 + 2 * tig;
            float2 gg = *(const float2*)(g2 + col);
            float2 bb = *(const float2*)(b2 + col);
            float2 sA = *(const float2*)(src + (size_t)(r0 + rA) * D + col);
            float2 sB = *(const float2*)(src + (size_t)(r0 + rB) * D + col);
            *(float2*)(out + (size_t)(r0 + rA) * D + col) =
                make_float2((c[mt][nt][0] - mA) * rsA * gg.x + bb.x + sA.x,
                            (c[mt][nt][1] - mA) * rsA * gg.y + bb.y + sA.y);
            *(float2*)(out + (size_t)(r0 + rB) * D + col) =
                make_float2((c[mt][nt][2] - mB) * rsB * gg.x + bb.x + sB.x,
                            (c[mt][nt][3] - mB) * rsB * gg.y + bb.y + sB.y);
        }
    }
}

// ------------------------- launch -------------------------
extern "C" void kernel_launch(void* const* d_in, const int* in_sizes, int n_in,
                              void* d_out, int out_size) {
    (void)in_sizes; (void)n_in; (void)out_size;
    const float* src  = (const float*)d_in[0];
    const float* tgt  = (const float*)d_in[1];
    const float* mask = (const float*)d_in[2];
    const float* Wq   = (const float*)d_in[8];
    const float* Wk   = (const float*)d_in[9];
    const float* Wv   = (const float*)d_in[10];
    const float* Wm   = (const float*)d_in[11];
    const float* g1   = (const float*)d_in[12];
    const float* b1   = (const float*)d_in[13];
    const float* W1   = (const float*)d_in[14];
    const float* W2   = (const float*)d_in[15];
    const float* g2   = (const float*)d_in[16];
    const float* b2   = (const float*)d_in[17];
    float* out = (float*)d_out;

    k_qkv<<<dim3(256, 3), 256>>>(src, tgt, Wq, Wk, Wv);
    k_scores<<<dim3(16, 16, 16), 256>>>(mask);
    k_softmax<<<NWIN * LWIN, 256>>>();
    k_pv<<<dim3(16, 16), 256>>>();
    k_msg<<<256, 256>>>(Wm, g1, b1);
    k_h<<<dim3(256, 8), 256>>>(src, W1);
    k_out<<<256, 256>>>(src, W2, g2, b2, out);
}

// round 11
// speedup vs baseline: 2.4307x; 1.1565x over previous
#include <cuda_runtime.h>
#include <math.h>

// Problem dims (hardcoded per reference): B=4, H=64, W=128, D=128, NS=2
#define D 128
#define LWIN 2048
#define NWIN 16
#define NTOK 32768
#define LDT 132   // padded leading dim for staged smem tiles (kills bank conflicts)

// ------------------------- scratch (static device memory) -------------------------
__device__ float g_q[NWIN * LWIN * D];                 // windowed q (tf32-rounded fp32)
__device__ float g_k[NWIN * LWIN * D];                 // windowed k (tf32-rounded)
__device__ float g_v[NWIN * LWIN * D];                 // windowed v (tf32-rounded)
__device__ float g_ao[NWIN * LWIN * D];                // windowed attn out (fp32)
__device__ float g_msg[NTOK * D];                      // LN(attn@Wm) original order (fp32)
__device__ float g_h[(size_t)NTOK * 1024];             // gelu hidden (tf32-rounded) 134MB

// ------------------------- index maps (roll + window partition fused) --------------
__device__ __forceinline__ int win_to_src(int w, int l) {
    int b = w >> 2, wi = w & 3;
    int i = wi >> 1, j = wi & 1;
    int y = l >> 6, x = l & 63;            // hh=32, ww=64
    int ys = i * 32 + y, xs = j * 64 + x;
    int yo = (ys + 16) & 63, xo = (xs + 32) & 127;
    return (b << 13) + (yo << 7) + xo;
}
__device__ __forceinline__ int src_to_win(int r) {
    int b = r >> 13, yo = (r >> 7) & 63, xo = r & 127;
    int ym = (yo + 48) & 63, xm = (xo + 96) & 127;
    int i = ym >> 5, y = ym & 31;
    int j = xm >> 6, x = xm & 63;
    int w = (b << 2) + (i << 1) + j;
    int l = (y << 6) + x;
    return w * LWIN + l;
}

// ------------------------- tf32 helpers -------------------------
__device__ __forceinline__ unsigned f2tf(float x) {
    unsigned r; asm("cvt.rna.tf32.f32 %0, %1;" : "=r"(r) : "f"(x)); return r;
}
__device__ __forceinline__ float tf32r(float x) { return __uint_as_float(f2tf(x)); }

__device__ __forceinline__ void mma8(float* c, const unsigned* a, const unsigned* b) {
    asm volatile("mma.sync.aligned.m16n8k8.row.col.f32.tf32.tf32.f32 "
                 "{%0,%1,%2,%3}, {%4,%5,%6,%7}, {%8,%9}, {%0,%1,%2,%3};\n"
                 : "+f"(c[0]), "+f"(c[1]), "+f"(c[2]), "+f"(c[3])
                 : "r"(a[0]), "r"(a[1]), "r"(a[2]), "r"(a[3]), "r"(b[0]), "r"(b[1]));
}

// ------------------------- staging -------------------------
// transpose-stage 128 rows x 16 k of row-major src -> dst[k][m] (LDT-padded)
template <bool CVT>
__device__ __forceinline__ void stT(float* dst, const float* __restrict__ src,
                                    size_t ld, int k0, int tid) {
    int m = tid >> 1, ks = (tid & 1) * 8;
    const float* p = src + (size_t)m * ld + k0 + ks;
    float4 v0 = *(const float4*)p, v1 = *(const float4*)(p + 4);
    float vv[8] = {v0.x, v0.y, v0.z, v0.w, v1.x, v1.y, v1.z, v1.w};
#pragma unroll
    for (int j = 0; j < 8; j++)
        dst[(ks + j) * LDT + m] = CVT ? tf32r(vv[j]) : vv[j];
}
// transpose-stage with scale + tf32 round (for Q)
__device__ __forceinline__ void stT_scale(float* dst, const float* __restrict__ src,
                                          size_t ld, int k0, int tid, float scale) {
    int m = tid >> 1, ks = (tid & 1) * 8;
    const float* p = src + (size_t)m * ld + k0 + ks;
    float4 v0 = *(const float4*)p, v1 = *(const float4*)(p + 4);
    float vv[8] = {v0.x, v0.y, v0.z, v0.w, v1.x, v1.y, v1.z, v1.w};
#pragma unroll
    for (int j = 0; j < 8; j++)
        dst[(ks + j) * LDT + m] = tf32r(vv[j] * scale);
}
// gathered transpose-stage via rowmap (D-wide rows)
template <bool CVT>
__device__ __forceinline__ void stTg(float* dst, const float* __restrict__ src,
                                     const int* __restrict__ rowmap, int k0, int tid) {
    int m = tid >> 1, ks = (tid & 1) * 8;
    const float* p = src + (size_t)rowmap[m] * D + k0 + ks;
    float4 v0 = *(const float4*)p, v1 = *(const float4*)(p + 4);
    float vv[8] = {v0.x, v0.y, v0.z, v0.w, v1.x, v1.y, v1.z, v1.w};
#pragma unroll
    for (int j = 0; j < 8; j++)
        dst[(ks + j) * LDT + m] = CVT ? tf32r(vv[j]) : vv[j];
}
// direct stage of k-major B rows: dst[k][n] = src[(k0+k)*ld + n], n in [0,128)
template <bool CVT>
__device__ __forceinline__ void stK(float* dst, const float* __restrict__ src,
                                    size_t ld, int k0, int tid) {
    int kk = tid >> 4, n = (tid & 15) * 8;
    const float* p = src + (size_t)(k0 + kk) * ld + n;
    float4 v0 = *(const float4*)p, v1 = *(const float4*)(p + 4);
    if (CVT) {
        v0.x = tf32r(v0.x); v0.y = tf32r(v0.y); v0.z = tf32r(v0.z); v0.w = tf32r(v0.w);
        v1.x = tf32r(v1.x); v1.y = tf32r(v1.y); v1.z = tf32r(v1.z); v1.w = tf32r(v1.w);
    }
    *(float4*)(dst + kk * LDT + n) = v0;
    *(float4*)(dst + kk * LDT + n + 4) = v1;
}

// ------------------------- mma compute on one BK=16 stage -------------------------
// warps 4x2 (wy,wx), warp tile 32m x 64n, c[2 mtiles][8 ntiles][4]
__device__ __forceinline__ void mma_stage(const float* As, const float* Bs,
                                          float c[2][8][4], int wy, int wx, int g, int tig) {
#pragma unroll
    for (int k8 = 0; k8 < 16; k8 += 8) {
        unsigned a[2][4], b[8][2];
#pragma unroll
        for (int mt = 0; mt < 2; mt++) {
            int mb = wy * 32 + mt * 16;
            a[mt][0] = __float_as_uint(As[(k8 + tig) * LDT + mb + g]);
            a[mt][1] = __float_as_uint(As[(k8 + tig) * LDT + mb + 8 + g]);
            a[mt][2] = __float_as_uint(As[(k8 + tig + 4) * LDT + mb + g]);
            a[mt][3] = __float_as_uint(As[(k8 + tig + 4) * LDT + mb + 8 + g]);
        }
#pragma unroll
        for (int nt = 0; nt < 8; nt++) {
            int nb = wx * 64 + nt * 8;
            b[nt][0] = __float_as_uint(Bs[(k8 + tig) * LDT + nb + g]);
            b[nt][1] = __float_as_uint(Bs[(k8 + tig + 4) * LDT + nb + g]);
        }
#pragma unroll
        for (int mt = 0; mt < 2; mt++)
#pragma unroll
            for (int nt = 0; nt < 8; nt++) mma8(c[mt][nt], a[mt], b[nt]);
    }
}

// ------------------------- K1: QKV projection (mma, gathered, tf32-rounded out) ------
__global__ void __launch_bounds__(256) k_qkv(const float* __restrict__ src,
                                             const float* __restrict__ tgt,
                                             const float* __restrict__ Wq,
                                             const float* __restrict__ Wk,
                                             const float* __restrict__ Wv) {
    __shared__ float As[16 * LDT], Bs[16 * LDT];
    __shared__ int rowmap[128];
    int tid = threadIdx.x;
    int which = blockIdx.y;
    const float* A = (which == 0) ? src : tgt;
    const float* W = (which == 0) ? Wq : (which == 1 ? Wk : Wv);
    float* out = (which == 0) ? g_q : (which == 1 ? g_k : g_v);
    int t0 = blockIdx.x * 128;
    if (tid < 128) { int t = t0 + tid; rowmap[tid] = win_to_src(t >> 11, t & 2047); }
    __syncthreads();
    int warp = tid >> 5, lane = tid & 31, wy = warp >> 1, wx = warp & 1;
    int g = lane >> 2, tig = lane & 3;
    float c[2][8][4] = {};
    for (int k0 = 0; k0 < 128; k0 += 16) {
        stTg<true>(As, A, rowmap, k0, tid);
        stK<true>(Bs, W, 128, k0, tid);
        __syncthreads();
        mma_stage(As, Bs, c, wy, wx, g, tig);
        __syncthreads();
    }
#pragma unroll
    for (int mt = 0; mt < 2; mt++) {
        int r = t0 + wy * 32 + mt * 16 + g;
#pragma unroll
        for (int nt = 0; nt < 8; nt++) {
            int col = wx * 64 + nt * 8 + 2 * tig;
            *(float2*)(out + (size_t)r * D + col) =
                make_float2(tf32r(c[mt][nt][0]), tf32r(c[mt][nt][1]));
            *(float2*)(out + (size_t)(r + 8) * D + col) =
                make_float2(tf32r(c[mt][nt][2]), tf32r(c[mt][nt][3]));
        }
    }
}

// ------------------------- K2: fused flash attention per window -------------------------
// grid (16 q-tiles, 16 windows), 256 threads. S never touches DRAM.
#define ATTN_SMEM ((3 * 128 * LDT + 512) * 4)
__global__ void __launch_bounds__(256, 1) k_attn(const float* __restrict__ mask) {
    extern __shared__ float sm[];
    float* Qs  = sm;                       // [128 k][LDT m]  Q^T, pre-scaled tf32
    float* Ps  = sm + 128 * LDT;           // [128 kc][LDT m] P^T tf32
    float* KVs = sm + 2 * 128 * LDT;       // K^T (QK phase) then V (PV phase)
    float* smax = sm + 3 * 128 * LDT;      // [2][128]
    float* ssum = smax + 256;              // [2][128]

    int tid = threadIdx.x;
    int m0 = blockIdx.x * 128, w = blockIdx.y;
    const float* Qbase = g_q + ((size_t)w * LWIN + m0) * D;
    const float* Kwin = g_k + (size_t)w * LWIN * D;
    const float* Vwin = g_v + (size_t)w * LWIN * D;
    const float* M = mask + (size_t)(w & 3) * LWIN * LWIN;

    int warp = tid >> 5, lane = tid & 31, wy = warp >> 1, wx = warp & 1;
    int g = lane >> 2, tig = lane & 3;

    const float scale = 0.08838834764831845f;  // 1/sqrt(128)
    for (int k0 = 0; k0 < 128; k0 += 16)
        stT_scale(Qs + k0 * LDT, Qbase, D, k0, tid, scale);

    float o_acc[2][8][4] = {};
    // 4 row-slots per thread: s -> local row = wy*32 + (s>>1)*16 + g + 8*(s&1)
    float m_run[4] = {-INFINITY, -INFINITY, -INFINITY, -INFINITY};
    float l_run[4] = {0.f, 0.f, 0.f, 0.f};

    for (int kt = 0; kt < 16; kt++) {
        __syncthreads();  // prev PV reads of Ps/KVs done before overwrite
        const float* Kbase = Kwin + (size_t)kt * 128 * D;
        for (int k0 = 0; k0 < 128; k0 += 16)
            stT<false>(KVs + k0 * LDT, Kbase, D, k0, tid);
        __syncthreads();

        float s_acc[2][8][4] = {};
        for (int d0 = 0; d0 < 128; d0 += 16)
            mma_stage(Qs + d0 * LDT, KVs + d0 * LDT, s_acc, wy, wx, g, tig);

        // mask add + per-slot tile max
        float tmax[4] = {-INFINITY, -INFINITY, -INFINITY, -INFINITY};
#pragma unroll
        for (int mt = 0; mt < 2; mt++) {
            int rA = m0 + wy * 32 + mt * 16 + g;
#pragma unroll
            for (int nt = 0; nt < 8; nt++) {
                int col = kt * 128 + wx * 64 + nt * 8 + 2 * tig;
                float2 mk0 = *(const float2*)(M + (size_t)rA * LWIN + col);
                float2 mk1 = *(const float2*)(M + (size_t)(rA + 8) * LWIN + col);
                s_acc[mt][nt][0] += mk0.x;
                s_acc[mt][nt][1] += mk0.y;
                s_acc[mt][nt][2] += mk1.x;
                s_acc[mt][nt][3] += mk1.y;
                tmax[mt * 2]     = fmaxf(tmax[mt * 2],     fmaxf(s_acc[mt][nt][0], s_acc[mt][nt][1]));
                tmax[mt * 2 + 1] = fmaxf(tmax[mt * 2 + 1], fmaxf(s_acc[mt][nt][2], s_acc[mt][nt][3]));
            }
        }
#pragma unroll
        for (int s = 0; s < 4; s++) {
            tmax[s] = fmaxf(tmax[s], __shfl_xor_sync(0xffffffffu, tmax[s], 1));
            tmax[s] = fmaxf(tmax[s], __shfl_xor_sync(0xffffffffu, tmax[s], 2));
        }
        if (tig == 0) {
#pragma unroll
            for (int s = 0; s < 4; s++) {
                int r = wy * 32 + (s >> 1) * 16 + g + 8 * (s & 1);
                smax[wx * 128 + r] = tmax[s];
            }
        }
        __syncthreads();  // smax ready; all QK reads of KVs done

        float alpha[4], m_new[4], psum[4];
#pragma unroll
        for (int s = 0; s < 4; s++) {
            int r = wy * 32 + (s >> 1) * 16 + g + 8 * (s & 1);
            float mt_tile = fmaxf(smax[r], smax[128 + r]);
            m_new[s] = fmaxf(m_run[s], mt_tile);
            alpha[s] = __expf(m_run[s] - m_new[s]);
            m_run[s] = m_new[s];
            psum[s] = 0.f;
        }
#pragma unroll
        for (int mt = 0; mt < 2; mt++) {
            int rA = wy * 32 + mt * 16 + g;
#pragma unroll
            for (int nt = 0; nt < 8; nt++) {
                int colb = wx * 64 + nt * 8 + 2 * tig;
                float p0 = __expf(s_acc[mt][nt][0] - m_new[mt * 2]);
                float p1 = __expf(s_acc[mt][nt][1] - m_new[mt * 2]);
                float p2 = __expf(s_acc[mt][nt][2] - m_new[mt * 2 + 1]);
                float p3 = __expf(s_acc[mt][nt][3] - m_new[mt * 2 + 1]);
                psum[mt * 2]     += p0 + p1;
                psum[mt * 2 + 1] += p2 + p3;
                Ps[colb * LDT + rA]           = tf32r(p0);
                Ps[(colb + 1) * LDT + rA]     = tf32r(p1);
                Ps[colb * LDT + rA + 8]       = tf32r(p2);
                Ps[(colb + 1) * LDT + rA + 8] = tf32r(p3);
                o_acc[mt][nt][0] *= alpha[mt * 2];
                o_acc[mt][nt][1] *= alpha[mt * 2];
                o_acc[mt][nt][2] *= alpha[mt * 2 + 1];
                o_acc[mt][nt][3] *= alpha[mt * 2 + 1];
            }
        }
#pragma unroll
        for (int s = 0; s < 4; s++) {
            psum[s] += __shfl_xor_sync(0xffffffffu, psum[s], 1);
            psum[s] += __shfl_xor_sync(0xffffffffu, psum[s], 2);
        }
        if (tig == 0) {
#pragma unroll
            for (int s = 0; s < 4; s++) {
                int r = wy * 32 + (s >> 1) * 16 + g + 8 * (s & 1);
                ssum[wx * 128 + r] = psum[s];
            }
        }
        // stage V (reuses KVs; QK reads fenced by the barrier above)
        const float* Vbase = Vwin + (size_t)kt * 128 * D;
        for (int r0 = 0; r0 < 128; r0 += 16)
            stK<false>(KVs + r0 * LDT, Vbase, D, r0, tid);
        __syncthreads();  // Ps, Vs, ssum ready

#pragma unroll
        for (int s = 0; s < 4; s++) {
            int r = wy * 32 + (s >> 1) * 16 + g + 8 * (s & 1);
            l_run[s] = l_run[s] * alpha[s] + ssum[r] + ssum[128 + r];
        }
        for (int kc0 = 0; kc0 < 128; kc0 += 16)
            mma_stage(Ps + kc0 * LDT, KVs + kc0 * LDT, o_acc, wy, wx, g, tig);
    }

    // normalize + write windowed attn out
    float inv[4];
#pragma unroll
    for (int s = 0; s < 4; s++) inv[s] = 1.0f / l_run[s];
    float* O = g_ao + (size_t)(w * LWIN + m0) * D;
#pragma unroll
    for (int mt = 0; mt < 2; mt++) {
        int rA = wy * 32 + mt * 16 + g;
#pragma unroll
        for (int nt = 0; nt < 8; nt++) {
            int col = wx * 64 + nt * 8 + 2 * tig;
            *(float2*)(O + (size_t)rA * D + col) =
                make_float2(o_acc[mt][nt][0] * inv[mt * 2], o_acc[mt][nt][1] * inv[mt * 2]);
            *(float2*)(O + (size_t)(rA + 8) * D + col) =
                make_float2(o_acc[mt][nt][2] * inv[mt * 2 + 1], o_acc[mt][nt][3] * inv[mt * 2 + 1]);
        }
    }
}

// ------------------------- K5: msg = LN((window-merged O) @ Wm) ----------------------
__global__ void __launch_bounds__(256) k_msg(const float* __restrict__ Wm,
                                             const float* __restrict__ g1,
                                             const float* __restrict__ b1) {
    __shared__ float As[16 * LDT], Bs[16 * LDT];
    __shared__ int rowmap[128];
    __shared__ float red1[2 * 128], red2[2 * 128];
    int tid = threadIdx.x;
    int r0 = blockIdx.x * 128;
    if (tid < 128) rowmap[tid] = src_to_win(r0 + tid);
    __syncthreads();
    int warp = tid >> 5, lane = tid & 31, wy = warp >> 1, wx = warp & 1;
    int g = lane >> 2, tig = lane & 3;
    float c[2][8][4] = {};
    for (int k0 = 0; k0 < 128; k0 += 16) {
        stTg<true>(As, g_ao, rowmap, k0, tid);
        stK<true>(Bs, Wm, 128, k0, tid);
        __syncthreads();
        mma_stage(As, Bs, c, wy, wx, g, tig);
        __syncthreads();
    }
#pragma unroll
    for (int mt = 0; mt < 2; mt++) {
        float sA1 = 0.f, sA2 = 0.f, sB1 = 0.f, sB2 = 0.f;
#pragma unroll
        for (int nt = 0; nt < 8; nt++) {
            sA1 += c[mt][nt][0] + c[mt][nt][1];
            sA2 += c[mt][nt][0] * c[mt][nt][0] + c[mt][nt][1] * c[mt][nt][1];
            sB1 += c[mt][nt][2] + c[mt][nt][3];
            sB2 += c[mt][nt][2] * c[mt][nt][2] + c[mt][nt][3] * c[mt][nt][3];
        }
#pragma unroll
        for (int o = 1; o < 4; o <<= 1) {
            sA1 += __shfl_xor_sync(0xffffffffu, sA1, o);
            sA2 += __shfl_xor_sync(0xffffffffu, sA2, o);
            sB1 += __shfl_xor_sync(0xffffffffu, sB1, o);
            sB2 += __shfl_xor_sync(0xffffffffu, sB2, o);
        }
        if (tig == 0) {
            int rA = wy * 32 + mt * 16 + g, rB = rA + 8;
            red1[wx * 128 + rA] = sA1; red2[wx * 128 + rA] = sA2;
            red1[wx * 128 + rB] = sB1; red2[wx * 128 + rB] = sB2;
        }
    }
    __syncthreads();
#pragma unroll
    for (int mt = 0; mt < 2; mt++) {
        int rA = wy * 32 + mt * 16 + g, rB = rA + 8;
        float mA = (red1[rA] + red1[128 + rA]) * (1.0f / 128.0f);
        float vA = (red2[rA] + red2[128 + rA]) * (1.0f / 128.0f) - mA * mA;
        float rsA = rsqrtf(vA + 1e-5f);
        float mB = (red1[rB] + red1[128 + rB]) * (1.0f / 128.0f);
        float vB = (red2[rB] + red2[128 + rB]) * (1.0f / 128.0f) - mB * mB;
        float rsB = rsqrtf(vB + 1e-5f);
#pragma unroll
        for (int nt = 0; nt < 8; nt++) {
            int col = wx * 64 + nt * 8 + 2 * tig;
            float2 gg = *(const float2*)(g1 + col);
            float2 bb = *(const float2*)(b1 + col);
            *(float2*)(g_msg + (size_t)(r0 + rA) * D + col) =
                make_float2((c[mt][nt][0] - mA) * rsA * gg.x + bb.x,
                            (c[mt][nt][1] - mA) * rsA * gg.y + bb.y);
            *(float2*)(g_msg + (size_t)(r0 + rB) * D + col) =
                make_float2((c[mt][nt][2] - mB) * rsB * gg.x + bb.x,
                            (c[mt][nt][3] - mB) * rsB * gg.y + bb.y);
        }
    }
}

// ------------------------- K6: h = gelu(concat(src,msg) @ W1) ------------------------
__global__ void __launch_bounds__(256) k_h(const float* __restrict__ src,
                                           const float* __restrict__ W1) {
    __shared__ float As[16 * LDT], Bs[16 * LDT];
    int tid = threadIdx.x;
    int r0 = blockIdx.x * 128;
    int nch = blockIdx.y * 128;
    int warp = tid >> 5, lane = tid & 31, wy = warp >> 1, wx = warp & 1;
    int g = lane >> 2, tig = lane & 3;
    float c[2][8][4] = {};
    for (int k0 = 0; k0 < 256; k0 += 16) {
        if (k0 < 128) stT<true>(As, src + (size_t)r0 * D, D, k0, tid);
        else          stT<true>(As, g_msg + (size_t)r0 * D, D, k0 - 128, tid);
        stK<true>(Bs, W1 + nch, 1024, k0, tid);
        __syncthreads();
        mma_stage(As, Bs, c, wy, wx, g, tig);
        __syncthreads();
    }
#pragma unroll
    for (int mt = 0; mt < 2; mt++) {
        int r = r0 + wy * 32 + mt * 16 + g;
#pragma unroll
        for (int nt = 0; nt < 8; nt++) {
            int col = nch + wx * 64 + nt * 8 + 2 * tig;
            float o[4];
#pragma unroll
            for (int j = 0; j < 4; j++) {
                float x = c[mt][nt][j];
                o[j] = tf32r(0.5f * x * (1.0f + erff(x * 0.70710678118654752f)));
            }
            *(float2*)(g_h + (size_t)r * 1024 + col) = make_float2(o[0], o[1]);
            *(float2*)(g_h + (size_t)(r + 8) * 1024 + col) = make_float2(o[2], o[3]);
        }
    }
}

// ------------------------- K7: out = src + LN(h @ W2) -------------------------
__global__ void __launch_bounds__(256) k_out(const float* __restrict__ src,
                                             const float* __restrict__ W2,
                                             const float* __restrict__ g2,
                                             const float* __restrict__ b2,
                                             float* __restrict__ out) {
    __shared__ float As[16 * LDT], Bs[16 * LDT];
    __shared__ float red1[2 * 128], red2[2 * 128];
    int tid = threadIdx.x;
    int r0 = blockIdx.x * 128;
    int warp = tid >> 5, lane = tid & 31, wy = warp >> 1, wx = warp & 1;
    int g = lane >> 2, tig = lane & 3;
    float c[2][8][4] = {};
    for (int k0 = 0; k0 < 1024; k0 += 16) {
        stT<false>(As, g_h + (size_t)r0 * 1024, 1024, k0, tid);
        stK<true>(Bs, W2, 128, k0, tid);
        __syncthreads();
        mma_stage(As, Bs, c, wy, wx, g, tig);
        __syncthreads();
    }
#pragma unroll
    for (int mt = 0; mt < 2; mt++) {
        float sA1 = 0.f, sA2 = 0.f, sB1 = 0.f, sB2 = 0.f;
#pragma unroll
        for (int nt = 0; nt < 8; nt++) {
            sA1 += c[mt][nt][0] + c[mt][nt][1];
            sA2 += c[mt][nt][0] * c[mt][nt][0] + c[mt][nt][1] * c[mt][nt][1];
            sB1 += c[mt][nt][2] + c[mt][nt][3];
            sB2 += c[mt][nt][2] * c[mt][nt][2] + c[mt][nt][3] * c[mt][nt][3];
        }
#pragma unroll
        for (int o = 1; o < 4; o <<= 1) {
            sA1 += __shfl_xor_sync(0xffffffffu, sA1, o);
            sA2 += __shfl_xor_sync(0xffffffffu, sA2, o);
            sB1 += __shfl_xor_sync(0xffffffffu, sB1, o);
            sB2 += __shfl_xor_sync(0xffffffffu, sB2, o);
        }
        if (tig == 0) {
            int rA = wy * 32 + mt * 16 + g, rB = rA + 8;
            red1[wx * 128 + rA] = sA1; red2[wx * 128 + rA] = sA2;
            red1[wx * 128 + rB] = sB1; red2[wx * 128 + rB] = sB2;
        }
    }
    __syncthreads();
#pragma unroll
    for (int mt = 0; mt < 2; mt++) {
        int rA = wy * 32 + mt * 16 + g, rB = rA + 8;
        float mA = (red1[rA] + red1[128 + rA]) * (1.0f / 128.0f);
        float vA = (red2[rA] + red2[128 + rA]) * (1.0f / 128.0f) - mA * mA;
        float rsA = rsqrtf(vA + 1e-5f);
        float mB = (red1[rB] + red1[128 + rB]) * (1.0f / 128.0f);
        float vB = (red2[rB] + red2[128 + rB]) * (1.0f / 128.0f) - mB * mB;
        float rsB = rsqrtf(vB + 1e-5f);
#pragma unroll
        for (int nt = 0; nt < 8; nt++) {
            int col = wx * 64 + nt * 8 + 2 * tig;
            float2 gg = *(const float2*)(g2 + col);
            float2 bb = *(const float2*)(b2 + col);
            float2 sA = *(const float2*)(src + (size_t)(r0 + rA) * D + col);
            float2 sB = *(const float2*)(src + (size_t)(r0 + rB) * D + col);
            *(float2*)(out + (size_t)(r0 + rA) * D + col) =
                make_float2((c[mt][nt][0] - mA) * rsA * gg.x + bb.x + sA.x,
                            (c[mt][nt][1] - mA) * rsA * gg.y + bb.y + sA.y);
            *(float2*)(out + (size_t)(r0 + rB) * D + col) =
                make_float2((c[mt][nt][2] - mB) * rsB * gg.x + bb.x + sB.x,
                            (c[mt][nt][3] - mB) * rsB * gg.y + bb.y + sB.y);
        }
    }
}

// ------------------------- launch -------------------------
extern "C" void kernel_launch(void* const* d_in, const int* in_sizes, int n_in,
                              void* d_out, int out_size) {
    (void)in_sizes; (void)n_in; (void)out_size;
    const float* src  = (const float*)d_in[0];
    const float* tgt  = (const float*)d_in[1];
    const float* mask = (const float*)d_in[2];
    const float* Wq   = (const float*)d_in[8];
    const float* Wk   = (const float*)d_in[9];
    const float* Wv   = (const float*)d_in[10];
    const float* Wm   = (const float*)d_in[11];
    const float* g1   = (const float*)d_in[12];
    const float* b1   = (const float*)d_in[13];
    const float* W1   = (const float*)d_in[14];
    const float* W2   = (const float*)d_in[15];
    const float* g2   = (const float*)d_in[16];
    const float* b2   = (const float*)d_in[17];
    float* out = (float*)d_out;

    k_qkv<<<dim3(256, 3), 256>>>(src, tgt, Wq, Wk, Wv);
    cudaFuncSetAttribute(k_attn, cudaFuncAttributeMaxDynamicSharedMemorySize, ATTN_SMEM);
    k_attn<<<dim3(16, 16), 256, ATTN_SMEM>>>(mask);
    k_msg<<<256, 256>>>(Wm, g1, b1);
    k_h<<<dim3(256, 8), 256>>>(src, W1);
    k_out<<<256, 256>>>(src, W2, g2, b2, out);
}

// round 12
// speedup vs baseline: 2.8126x; 1.1571x over previous
#include <cuda_runtime.h>
#include <math.h>

// Problem dims (hardcoded per reference): B=4, H=64, W=128, D=128, NS=2
#define D 128
#define LWIN 2048
#define NWIN 16
#define NTOK 32768
#define LDT 132   // padded leading dim (conflict-free: 132g mod 32 = 4g)

// ------------------------- scratch (static device memory) -------------------------
__device__ float g_q[NWIN * LWIN * D];                 // windowed q (tf32-rounded)
__device__ float g_k[NWIN * LWIN * D];                 // windowed k (tf32-rounded)
__device__ float g_vT[NWIN * D * LWIN];                // windowed v TRANSPOSED [w][d][l], tf32
__device__ float g_ao[NWIN * LWIN * D];                // windowed attn out (fp32)
__device__ float g_msg[NTOK * D];                      // LN(attn@Wm) original order
__device__ float g_h[(size_t)NTOK * 1024];             // gelu hidden (tf32-rounded)

// ------------------------- index maps (roll + window partition fused) --------------
__device__ __forceinline__ int win_to_src(int w, int l) {
    int b = w >> 2, wi = w & 3;
    int i = wi >> 1, j = wi & 1;
    int y = l >> 6, x = l & 63;            // hh=32, ww=64
    int ys = i * 32 + y, xs = j * 64 + x;
    int yo = (ys + 16) & 63, xo = (xs + 32) & 127;
    return (b << 13) + (yo << 7) + xo;
}
__device__ __forceinline__ int src_to_win(int r) {
    int b = r >> 13, yo = (r >> 7) & 63, xo = r & 127;
    int ym = (yo + 48) & 63, xm = (xo + 96) & 127;
    int i = ym >> 5, y = ym & 31;
    int j = xm >> 6, x = xm & 63;
    int w = (b << 2) + (i << 1) + j;
    int l = (y << 6) + x;
    return w * LWIN + l;
}

// ------------------------- tf32 / mma helpers -------------------------
__device__ __forceinline__ unsigned f2tf(float x) {
    unsigned r; asm("cvt.rna.tf32.f32 %0, %1;" : "=r"(r) : "f"(x)); return r;
}
__device__ __forceinline__ float tf32r(float x) { return __uint_as_float(f2tf(x)); }

__device__ __forceinline__ void mma8(float* c, const unsigned* a, const unsigned* b) {
    asm volatile("mma.sync.aligned.m16n8k8.row.col.f32.tf32.tf32.f32 "
                 "{%0,%1,%2,%3}, {%4,%5,%6,%7}, {%8,%9}, {%0,%1,%2,%3};\n"
                 : "+f"(c[0]), "+f"(c[1]), "+f"(c[2]), "+f"(c[3])
                 : "r"(a[0]), "r"(a[1]), "r"(a[2]), "r"(a[3]), "r"(b[0]), "r"(b[1]));
}

// cp.async helpers
__device__ __forceinline__ void cp16(float* s, const float* g) {
    unsigned sa = (unsigned)__cvta_generic_to_shared(s);
    asm volatile("cp.async.cg.shared.global [%0], [%1], 16;" :: "r"(sa), "l"(g));
}
__device__ __forceinline__ void cp_commit() { asm volatile("cp.async.commit_group;"); }
template <int N>
__device__ __forceinline__ void cp_wait() { asm volatile("cp.async.wait_group %0;" :: "n"(N)); }

// ------------------------- dense-GEMM pieces (transposed-A layout, as before) -------
struct F8 { float4 x, y; };
__device__ __forceinline__ F8 ld8(const float* p) {
    F8 r; r.x = *(const float4*)p; r.y = *(const float4*)(p + 4); return r;
}
// A transpose-store: regs -> As[k][m] (LDT)
template <bool CVT>
__device__ __forceinline__ void stT8(float* dst, const F8& r, int tid) {
    int m = tid >> 1, ks = (tid & 1) * 8;
    float v[8] = {r.x.x, r.x.y, r.x.z, r.x.w, r.y.x, r.y.y, r.y.z, r.y.w};
#pragma unroll
    for (int j = 0; j < 8; j++) dst[(ks + j) * LDT + m] = CVT ? tf32r(v[j]) : v[j];
}
// B k-major store: regs -> Bs[k][n] (LDT)
template <bool CVT>
__device__ __forceinline__ void stK8(float* dst, const F8& r, int tid) {
    int kk = tid >> 4, n = (tid & 15) * 8;
    float v[8] = {r.x.x, r.x.y, r.x.z, r.x.w, r.y.x, r.y.y, r.y.z, r.y.w};
#pragma unroll
    for (int j = 0; j < 8; j++) dst[kk * LDT + n + j] = CVT ? tf32r(v[j]) : v[j];
}
__device__ __forceinline__ F8 ldT(const float* src, size_t ld, int k0, int tid) {
    int m = tid >> 1, ks = (tid & 1) * 8;
    return ld8(src + (size_t)m * ld + k0 + ks);
}
__device__ __forceinline__ F8 ldKm(const float* src, size_t ld, int k0, int tid) {
    int kk = tid >> 4, n = (tid & 15) * 8;
    return ld8(src + (size_t)(k0 + kk) * ld + n);
}

// mma on one staged BK=16: As[k][m], Bs[k][n] (both LDT), warps 4x2, 32m x 64n
__device__ __forceinline__ void mma_stage(const float* As, const float* Bs,
                                          float c[2][8][4], int wy, int wx, int g, int tig) {
#pragma unroll
    for (int k8 = 0; k8 < 16; k8 += 8) {
        unsigned a[2][4], b[8][2];
#pragma unroll
        for (int mt = 0; mt < 2; mt++) {
            int mb = wy * 32 + mt * 16;
            a[mt][0] = __float_as_uint(As[(k8 + tig) * LDT + mb + g]);
            a[mt][1] = __float_as_uint(As[(k8 + tig) * LDT + mb + 8 + g]);
            a[mt][2] = __float_as_uint(As[(k8 + tig + 4) * LDT + mb + g]);
            a[mt][3] = __float_as_uint(As[(k8 + tig + 4) * LDT + mb + 8 + g]);
        }
#pragma unroll
        for (int nt = 0; nt < 8; nt++) {
            int nb = wx * 64 + nt * 8;
            b[nt][0] = __float_as_uint(Bs[(k8 + tig) * LDT + nb + g]);
            b[nt][1] = __float_as_uint(Bs[(k8 + tig + 4) * LDT + nb + g]);
        }
#pragma unroll
        for (int mt = 0; mt < 2; mt++)
#pragma unroll
            for (int nt = 0; nt < 8; nt++) mma8(c[mt][nt], a[mt], b[nt]);
    }
}

// natural-A [m][lda] / n-major-B [n][ldb] 16-deep mma (attention)
template <int MT, int NT>
__device__ __forceinline__ void mma16_bn(const float* As, int lda, const float* Bs, int ldb,
                                         float c[MT][NT][4], int mb0, int nb0, int g, int tig) {
#pragma unroll
    for (int k8 = 0; k8 < 16; k8 += 8) {
        unsigned a[MT][4], b[NT][2];
#pragma unroll
        for (int mt = 0; mt < MT; mt++) {
            const float* ap = As + (mb0 + mt * 16 + g) * lda + k8 + tig;
            a[mt][0] = __float_as_uint(ap[0]);
            a[mt][1] = __float_as_uint(ap[8 * lda]);
            a[mt][2] = __float_as_uint(ap[4]);
            a[mt][3] = __float_as_uint(ap[8 * lda + 4]);
        }
#pragma unroll
        for (int nt = 0; nt < NT; nt++) {
            const float* bp = Bs + (nb0 + nt * 8 + g) * ldb + k8 + tig;
            b[nt][0] = __float_as_uint(bp[0]);
            b[nt][1] = __float_as_uint(bp[4]);
        }
#pragma unroll
        for (int mt = 0; mt < MT; mt++)
#pragma unroll
            for (int nt = 0; nt < NT; nt++) mma8(c[mt][nt], a[mt], b[nt]);
    }
}

// ------------------------- K1: QKV projection (pipelined) -------------------------
__global__ void __launch_bounds__(256) k_qkv(const float* __restrict__ src,
                                             const float* __restrict__ tgt,
                                             const float* __restrict__ Wq,
                                             const float* __restrict__ Wk,
                                             const float* __restrict__ Wv) {
    __shared__ float As[2][16 * LDT], Bs[2][16 * LDT];
    __shared__ int rowmap[128];
    int tid = threadIdx.x;
    int which = blockIdx.y;
    const float* A = (which == 0) ? src : tgt;
    const float* W = (which == 0) ? Wq : (which == 1 ? Wk : Wv);
    int t0 = blockIdx.x * 128;
    if (tid < 128) { int t = t0 + tid; rowmap[tid] = win_to_src(t >> 11, t & 2047); }
    __syncthreads();
    const float* rowp = A + (size_t)rowmap[tid >> 1] * D;  // per-thread gathered row
    int warp = tid >> 5, lane = tid & 31, wy = warp >> 1, wx = warp & 1;
    int g = lane >> 2, tig = lane & 3;
    float c[2][8][4] = {};
    const int NS = 8;
    int ks = (tid & 1) * 8;
    F8 ra = ld8(rowp + ks), rb = ldKm(W, 128, 0, tid);
    stT8<true>(As[0], ra, tid); stK8<true>(Bs[0], rb, tid);
    ra = ld8(rowp + 16 + ks); rb = ldKm(W, 128, 16, tid);
    __syncthreads();
    for (int i = 0; i < NS; i++) {
        int cur = i & 1;
        if (i + 1 < NS) { stT8<true>(As[cur ^ 1], ra, tid); stK8<true>(Bs[cur ^ 1], rb, tid); }
        if (i + 2 < NS) { ra = ld8(rowp + (i + 2) * 16 + ks); rb = ldKm(W, 128, (i + 2) * 16, tid); }
        mma_stage(As[cur], Bs[cur], c, wy, wx, g, tig);
        __syncthreads();
    }
    if (which < 2) {
        float* out = (which == 0) ? g_q : g_k;
#pragma unroll
        for (int mt = 0; mt < 2; mt++) {
            int r = t0 + wy * 32 + mt * 16 + g;
#pragma unroll
            for (int nt = 0; nt < 8; nt++) {
                int col = wx * 64 + nt * 8 + 2 * tig;
                *(float2*)(out + (size_t)r * D + col) =
                    make_float2(tf32r(c[mt][nt][0]), tf32r(c[mt][nt][1]));
                *(float2*)(out + (size_t)(r + 8) * D + col) =
                    make_float2(tf32r(c[mt][nt][2]), tf32r(c[mt][nt][3]));
            }
        }
    } else {
        // V written transposed: g_vT[w][d][l]
        int w = t0 >> 11, l0 = t0 & 2047;
        float* VT = g_vT + (size_t)w * D * LWIN;
#pragma unroll
        for (int mt = 0; mt < 2; mt++) {
            int l = l0 + wy * 32 + mt * 16 + g;
#pragma unroll
            for (int nt = 0; nt < 8; nt++) {
                int col = wx * 64 + nt * 8 + 2 * tig;
                VT[(size_t)col * LWIN + l]           = tf32r(c[mt][nt][0]);
                VT[(size_t)(col + 1) * LWIN + l]     = tf32r(c[mt][nt][1]);
                VT[(size_t)col * LWIN + l + 8]       = tf32r(c[mt][nt][2]);
                VT[(size_t)(col + 1) * LWIN + l + 8] = tf32r(c[mt][nt][3]);
            }
        }
    }
}

// ------------------------- K2: flash attention, cp.async pipelined -------------------
// layouts (floats): Qs[128][132] | Ks[2][64][132] | Vs[128][68] | Ps[128][68] | smax | ssum
#define A_QS 0
#define A_KS 16896
#define A_VS 33792
#define A_PS 42496
#define A_SMAX 51200
#define A_SSUM 51456
#define ATTN_SMEM (51712 * 4)

__global__ void __launch_bounds__(256, 1) k_attn(const float* __restrict__ mask) {
    extern __shared__ float sm[];
    float* Qs = sm + A_QS;
    float* KsB = sm + A_KS;
    float* Vs = sm + A_VS;
    float* Ps = sm + A_PS;
    float* smax = sm + A_SMAX;
    float* ssum = sm + A_SSUM;

    int tid = threadIdx.x;
    int m0 = blockIdx.x * 128, w = blockIdx.y;
    const float* Qbase = g_q + ((size_t)w * LWIN + m0) * D;
    const float* Kwin = g_k + (size_t)w * LWIN * D;
    const float* VTwin = g_vT + (size_t)w * D * LWIN;
    const float* M = mask + (size_t)(w & 3) * LWIN * LWIN;

    int warp = tid >> 5, lane = tid & 31, wy = warp >> 1, wx = warp & 1;
    int g = lane >> 2, tig = lane & 3;

    // stage Q natural [m][132], pre-scaled tf32
    {
        int m = tid >> 1, ks = (tid & 1) * 8;
        const float* qp = Qbase + (size_t)m * D + ks;
        float* qd = Qs + m * 132 + ks;
        const float scale = 0.08838834764831845f;
#pragma unroll
        for (int d0 = 0; d0 < 128; d0 += 16) {
            float4 v0 = *(const float4*)(qp + d0);
            float4 v1 = *(const float4*)(qp + d0 + 4);
            qd[d0 + 0] = tf32r(v0.x * scale); qd[d0 + 1] = tf32r(v0.y * scale);
            qd[d0 + 2] = tf32r(v0.z * scale); qd[d0 + 3] = tf32r(v0.w * scale);
            qd[d0 + 4] = tf32r(v1.x * scale); qd[d0 + 5] = tf32r(v1.y * scale);
            qd[d0 + 6] = tf32r(v1.z * scale); qd[d0 + 7] = tf32r(v1.w * scale);
        }
    }
    // prefetch K(0): 64 rows x 128 floats
#pragma unroll
    for (int j = 0; j < 8; j++) {
        int e = tid + j * 256, n = e >> 5, ci = (e & 31) * 4;
        cp16(KsB + n * 132 + ci, Kwin + (size_t)n * D + ci);
    }
    cp_commit();

    float o_acc[2][8][4] = {};
    float m_run[4] = {-INFINITY, -INFINITY, -INFINITY, -INFINITY};
    float l_run[4] = {0.f, 0.f, 0.f, 0.f};
    int cur = 0;

    for (int kt = 0; kt < 32; kt++) {
        __syncthreads();  // S0: PV(kt-1) done -> Vs/Ps safe to overwrite
        // prefetch V(kt): 128 d-rows x 64 floats from g_vT
#pragma unroll
        for (int j = 0; j < 8; j++) {
            int e = tid + j * 256, d2 = e >> 4, ci = (e & 15) * 4;
            cp16(Vs + d2 * 68 + ci, VTwin + (size_t)d2 * LWIN + kt * 64 + ci);
        }
        cp_commit();                 // pending: {K(kt), V(kt)}
        cp_wait<1>();                // K(kt) landed
        __syncthreads();             // S1: Kbuf visible to all warps
        const float* Kc = KsB + cur * (64 * 132);

        float s_acc[2][4][4] = {};
#pragma unroll
        for (int d0 = 0; d0 < 128; d0 += 16)
            mma16_bn<2, 4>(Qs + d0, 132, Kc + d0, 132, s_acc, wy * 32, wx * 32, g, tig);

        // prefetch K(kt+1) into other buffer (wraps harmlessly at kt=31)
        {
            int ktn = (kt + 1) & 31;
            float* Kn = KsB + (cur ^ 1) * (64 * 132);
#pragma unroll
            for (int j = 0; j < 8; j++) {
                int e = tid + j * 256, n = e >> 5, ci = (e & 31) * 4;
                cp16(Kn + n * 132 + ci, Kwin + ((size_t)ktn * 64 + n) * D + ci);
            }
            cp_commit();             // pending: {V(kt), K(kt+1)}
        }

        // mask add + per-slot tile max
        float tmax[4] = {-INFINITY, -INFINITY, -INFINITY, -INFINITY};
#pragma unroll
        for (int mt = 0; mt < 2; mt++) {
            int rg = m0 + wy * 32 + mt * 16 + g;
#pragma unroll
            for (int nt = 0; nt < 4; nt++) {
                int cg = kt * 64 + wx * 32 + nt * 8 + 2 * tig;
                float2 mk0 = *(const float2*)(M + (size_t)rg * LWIN + cg);
                float2 mk1 = *(const float2*)(M + (size_t)(rg + 8) * LWIN + cg);
                s_acc[mt][nt][0] += mk0.x;
                s_acc[mt][nt][1] += mk0.y;
                s_acc[mt][nt][2] += mk1.x;
                s_acc[mt][nt][3] += mk1.y;
                tmax[mt * 2]     = fmaxf(tmax[mt * 2],     fmaxf(s_acc[mt][nt][0], s_acc[mt][nt][1]));
                tmax[mt * 2 + 1] = fmaxf(tmax[mt * 2 + 1], fmaxf(s_acc[mt][nt][2], s_acc[mt][nt][3]));
            }
        }
#pragma unroll
        for (int s = 0; s < 4; s++) {
            tmax[s] = fmaxf(tmax[s], __shfl_xor_sync(0xffffffffu, tmax[s], 1));
            tmax[s] = fmaxf(tmax[s], __shfl_xor_sync(0xffffffffu, tmax[s], 2));
        }
        if (tig == 0) {
#pragma unroll
            for (int s = 0; s < 4; s++) {
                int r = wy * 32 + (s >> 1) * 16 + g + 8 * (s & 1);
                smax[wx * 128 + r] = tmax[s];
            }
        }
        cp_wait<1>();                // V(kt) landed (K(kt+1) still flying)
        __syncthreads();             // S2: smax + Vbuf visible

        float alpha[4], m_new[4], psum[4];
#pragma unroll
        for (int s = 0; s < 4; s++) {
            int r = wy * 32 + (s >> 1) * 16 + g + 8 * (s & 1);
            float mt_tile = fmaxf(smax[r], smax[128 + r]);
            m_new[s] = fmaxf(m_run[s], mt_tile);
            alpha[s] = __expf(m_run[s] - m_new[s]);
            m_run[s] = m_new[s];
            psum[s] = 0.f;
        }
#pragma unroll
        for (int mt = 0; mt < 2; mt++) {
            int rA = wy * 32 + mt * 16 + g;
#pragma unroll
            for (int nt = 0; nt < 4; nt++) {
                int cl = wx * 32 + nt * 8 + 2 * tig;
                float p0 = __expf(s_acc[mt][nt][0] - m_new[mt * 2]);
                float p1 = __expf(s_acc[mt][nt][1] - m_new[mt * 2]);
                float p2 = __expf(s_acc[mt][nt][2] - m_new[mt * 2 + 1]);
                float p3 = __expf(s_acc[mt][nt][3] - m_new[mt * 2 + 1]);
                psum[mt * 2]     += p0 + p1;
                psum[mt * 2 + 1] += p2 + p3;
                *(float2*)(Ps + rA * 68 + cl)       = make_float2(tf32r(p0), tf32r(p1));
                *(float2*)(Ps + (rA + 8) * 68 + cl) = make_float2(tf32r(p2), tf32r(p3));
            }
#pragma unroll
            for (int nt = 0; nt < 8; nt++) {
                o_acc[mt][nt][0] *= alpha[mt * 2];
                o_acc[mt][nt][1] *= alpha[mt * 2];
                o_acc[mt][nt][2] *= alpha[mt * 2 + 1];
                o_acc[mt][nt][3] *= alpha[mt * 2 + 1];
            }
        }
#pragma unroll
        for (int s = 0; s < 4; s++) {
            psum[s] += __shfl_xor_sync(0xffffffffu, psum[s], 1);
            psum[s] += __shfl_xor_sync(0xffffffffu, psum[s], 2);
        }
        if (tig == 0) {
#pragma unroll
            for (int s = 0; s < 4; s++) {
                int r = wy * 32 + (s >> 1) * 16 + g + 8 * (s & 1);
                ssum[wx * 128 + r] = psum[s];
            }
        }
        __syncthreads();             // S3: Ps + ssum visible
#pragma unroll
        for (int s = 0; s < 4; s++) {
            int r = wy * 32 + (s >> 1) * 16 + g + 8 * (s & 1);
            l_run[s] = l_run[s] * alpha[s] + ssum[r] + ssum[128 + r];
        }
#pragma unroll
        for (int kc0 = 0; kc0 < 64; kc0 += 16)
            mma16_bn<2, 8>(Ps + kc0, 68, Vs + kc0, 68, o_acc, wy * 32, wx * 64, g, tig);
        cur ^= 1;
    }

    float inv[4];
#pragma unroll
    for (int s = 0; s < 4; s++) inv[s] = 1.0f / l_run[s];
    float* O = g_ao + (size_t)(w * LWIN + m0) * D;
#pragma unroll
    for (int mt = 0; mt < 2; mt++) {
        int rA = wy * 32 + mt * 16 + g;
#pragma unroll
        for (int nt = 0; nt < 8; nt++) {
            int col = wx * 64 + nt * 8 + 2 * tig;
            *(float2*)(O + (size_t)rA * D + col) =
                make_float2(o_acc[mt][nt][0] * inv[mt * 2], o_acc[mt][nt][1] * inv[mt * 2]);
            *(float2*)(O + (size_t)(rA + 8) * D + col) =
                make_float2(o_acc[mt][nt][2] * inv[mt * 2 + 1], o_acc[mt][nt][3] * inv[mt * 2 + 1]);
        }
    }
}

// ------------------------- K5: msg = LN((window-merged O) @ Wm), pipelined -----------
__global__ void __launch_bounds__(256) k_msg(const float* __restrict__ Wm,
                                             const float* __restrict__ g1,
                                             const float* __restrict__ b1) {
    __shared__ float As[2][16 * LDT], Bs[2][16 * LDT];
    __shared__ int rowmap[128];
    __shared__ float red1[2 * 128], red2[2 * 128];
    int tid = threadIdx.x;
    int r0 = blockIdx.x * 128;
    if (tid < 128) rowmap[tid] = src_to_win(r0 + tid);
    __syncthreads();
    const float* rowp = g_ao + (size_t)rowmap[tid >> 1] * D;
    int warp = tid >> 5, lane = tid & 31, wy = warp >> 1, wx = warp & 1;
    int g = lane >> 2, tig = lane & 3;
    float c[2][8][4] = {};
    const int NS = 8;
    int ks = (tid & 1) * 8;
    F8 ra = ld8(rowp + ks), rb = ldKm(Wm, 128, 0, tid);
    stT8<true>(As[0], ra, tid); stK8<true>(Bs[0], rb, tid);
    ra = ld8(rowp + 16 + ks); rb = ldKm(Wm, 128, 16, tid);
    __syncthreads();
    for (int i = 0; i < NS; i++) {
        int cur = i & 1;
        if (i + 1 < NS) { stT8<true>(As[cur ^ 1], ra, tid); stK8<true>(Bs[cur ^ 1], rb, tid); }
        if (i + 2 < NS) { ra = ld8(rowp + (i + 2) * 16 + ks); rb = ldKm(Wm, 128, (i + 2) * 16, tid); }
        mma_stage(As[cur], Bs[cur], c, wy, wx, g, tig);
        __syncthreads();
    }
#pragma unroll
    for (int mt = 0; mt < 2; mt++) {
        float sA1 = 0.f, sA2 = 0.f, sB1 = 0.f, sB2 = 0.f;
#pragma unroll
        for (int nt = 0; nt < 8; nt++) {
            sA1 += c[mt][nt][0] + c[mt][nt][1];
            sA2 += c[mt][nt][0] * c[mt][nt][0] + c[mt][nt][1] * c[mt][nt][1];
            sB1 += c[mt][nt][2] + c[mt][nt][3];
            sB2 += c[mt][nt][2] * c[mt][nt][2] + c[mt][nt][3] * c[mt][nt][3];
        }
#pragma unroll
        for (int o = 1; o < 4; o <<= 1) {
            sA1 += __shfl_xor_sync(0xffffffffu, sA1, o);
            sA2 += __shfl_xor_sync(0xffffffffu, sA2, o);
            sB1 += __shfl_xor_sync(0xffffffffu, sB1, o);
            sB2 += __shfl_xor_sync(0xffffffffu, sB2, o);
        }
        if (tig == 0) {
            int rA = wy * 32 + mt * 16 + g, rB = rA + 8;
            red1[wx * 128 + rA] = sA1; red2[wx * 128 + rA] = sA2;
            red1[wx * 128 + rB] = sB1; red2[wx * 128 + rB] = sB2;
        }
    }
    __syncthreads();
#pragma unroll
    for (int mt = 0; mt < 2; mt++) {
        int rA = wy * 32 + mt * 16 + g, rB = rA + 8;
        float mA = (red1[rA] + red1[128 + rA]) * (1.0f / 128.0f);
        float vA = (red2[rA] + red2[128 + rA]) * (1.0f / 128.0f) - mA * mA;
        float rsA = rsqrtf(vA + 1e-5f);
        float mB = (red1[rB] + red1[128 + rB]) * (1.0f / 128.0f);
        float vB = (red2[rB] + red2[128 + rB]) * (1.0f / 128.0f) - mB * mB;
        float rsB = rsqrtf(vB + 1e-5f);
#pragma unroll
        for (int nt = 0; nt < 8; nt++) {
            int col = wx * 64 + nt * 8 + 2 * tig;
            float2 gg = *(const float2*)(g1 + col);
            float2 bb = *(const float2*)(b1 + col);
            *(float2*)(g_msg + (size_t)(r0 + rA) * D + col) =
                make_float2((c[mt][nt][0] - mA) * rsA * gg.x + bb.x,
                            (c[mt][nt][1] - mA) * rsA * gg.y + bb.y);
            *(float2*)(g_msg + (size_t)(r0 + rB) * D + col) =
                make_float2((c[mt][nt][2] - mB) * rsB * gg.x + bb.x,
                            (c[mt][nt][3] - mB) * rsB * gg.y + bb.y);
        }
    }
}

// ------------------------- K6: h = gelu(concat(src,msg) @ W1), pipelined -------------
__global__ void __launch_bounds__(256) k_h(const float* __restrict__ src,
                                           const float* __restrict__ W1) {
    __shared__ float As[2][16 * LDT], Bs[2][16 * LDT];
    int tid = threadIdx.x;
    int r0 = blockIdx.x * 128;
    int nch = blockIdx.y * 128;
    int warp = tid >> 5, lane = tid & 31, wy = warp >> 1, wx = warp & 1;
    int g = lane >> 2, tig = lane & 3;
    const float* rs = src + (size_t)(r0 + (tid >> 1)) * D;
    const float* rm = g_msg + (size_t)(r0 + (tid >> 1)) * D;
    int ks = (tid & 1) * 8;
    const float* Wb = W1 + nch;
    float c[2][8][4] = {};
    const int NS = 16;
    F8 ra = ld8(rs + ks), rb = ldKm(Wb, 1024, 0, tid);
    stT8<true>(As[0], ra, tid); stK8<true>(Bs[0], rb, tid);
    ra = ld8(rs + 16 + ks); rb = ldKm(Wb, 1024, 16, tid);
    __syncthreads();
    for (int i = 0; i < NS; i++) {
        int cur = i & 1;
        if (i + 1 < NS) { stT8<true>(As[cur ^ 1], ra, tid); stK8<true>(Bs[cur ^ 1], rb, tid); }
        if (i + 2 < NS) {
            int k0 = (i + 2) * 16;
            ra = (k0 < 128) ? ld8(rs + k0 + ks) : ld8(rm + k0 - 128 + ks);
            rb = ldKm(Wb, 1024, k0, tid);
        }
        mma_stage(As[cur], Bs[cur], c, wy, wx, g, tig);
        __syncthreads();
    }
#pragma unroll
    for (int mt = 0; mt < 2; mt++) {
        int r = r0 + wy * 32 + mt * 16 + g;
#pragma unroll
        for (int nt = 0; nt < 8; nt++) {
            int col = nch + wx * 64 + nt * 8 + 2 * tig;
            float o[4];
#pragma unroll
            for (int j = 0; j < 4; j++) {
                float x = c[mt][nt][j];
                o[j] = tf32r(0.5f * x * (1.0f + erff(x * 0.70710678118654752f)));
            }
            *(float2*)(g_h + (size_t)r * 1024 + col) = make_float2(o[0], o[1]);
            *(float2*)(g_h + (size_t)(r + 8) * 1024 + col) = make_float2(o[2], o[3]);
        }
    }
}

// ------------------------- K7: out = src + LN(h @ W2), pipelined -------------------------
__global__ void __launch_bounds__(256) k_out(const float* __restrict__ src,
                                             const float* __restrict__ W2,
                                             const float* __restrict__ g2,
                                             const float* __restrict__ b2,
                                             float* __restrict__ out) {
    __shared__ float As[2][16 * LDT], Bs[2][16 * LDT];
    __shared__ float red1[2 * 128], red2[2 * 128];
    int tid = threadIdx.x;
    int r0 = blockIdx.x * 128;
    int warp = tid >> 5, lane = tid & 31, wy = warp >> 1, wx = warp & 1;
    int g = lane >> 2, tig = lane & 3;
    const float* rh = g_h + (size_t)(r0 + (tid >> 1)) * 1024;
    int ks = (tid & 1) * 8;
    float c[2][8][4] = {};
    const int NS = 64;
    F8 ra = ld8(rh + ks), rb = ldKm(W2, 128, 0, tid);
    stT8<false>(As[0], ra, tid); stK8<true>(Bs[0], rb, tid);
    ra = ld8(rh + 16 + ks); rb = ldKm(W2, 128, 16, tid);
    __syncthreads();
    for (int i = 0; i < NS; i++) {
        int cur = i & 1;
        if (i + 1 < NS) { stT8<false>(As[cur ^ 1], ra, tid); stK8<true>(Bs[cur ^ 1], rb, tid); }
        if (i + 2 < NS) { ra = ld8(rh + (i + 2) * 16 + ks); rb = ldKm(W2, 128, (i + 2) * 16, tid); }
        mma_stage(As[cur], Bs[cur], c, wy, wx, g, tig);
        __syncthreads();
    }
#pragma unroll
    for (int mt = 0; mt < 2; mt++) {
        float sA1 = 0.f, sA2 = 0.f, sB1 = 0.f, sB2 = 0.f;
#pragma unroll
        for (int nt = 0; nt < 8; nt++) {
            sA1 += c[mt][nt][0] + c[mt][nt][1];
            sA2 += c[mt][nt][0] * c[mt][nt][0] + c[mt][nt][1] * c[mt][nt][1];
            sB1 += c[mt][nt][2] + c[mt][nt][3];
            sB2 += c[mt][nt][2] * c[mt][nt][2] + c[mt][nt][3] * c[mt][nt][3];
        }
#pragma unroll
        for (int o = 1; o < 4; o <<= 1) {
            sA1 += __shfl_xor_sync(0xffffffffu, sA1, o);
            sA2 += __shfl_xor_sync(0xffffffffu, sA2, o);
            sB1 += __shfl_xor_sync(0xffffffffu, sB1, o);
            sB2 += __shfl_xor_sync(0xffffffffu, sB2, o);
        }
        if (tig == 0) {
            int rA = wy * 32 + mt * 16 + g, rB = rA + 8;
            red1[wx * 128 + rA] = sA1; red2[wx * 128 + rA] = sA2;
            red1[wx * 128 + rB] = sB1; red2[wx * 128 + rB] = sB2;
        }
    }
    __syncthreads();
#pragma unroll
    for (int mt = 0; mt < 2; mt++) {
        int rA = wy * 32 + mt * 16 + g, rB = rA + 8;
        float mA = (red1[rA] + red1[128 + rA]) * (1.0f / 128.0f);
        float vA = (red2[rA] + red2[128 + rA]) * (1.0f / 128.0f) - mA * mA;
        float rsA = rsqrtf(vA + 1e-5f);
        float mB = (red1[rB] + red1[128 + rB]) * (1.0f / 128.0f);
        float vB = (red2[rB] + red2[128 + rB]) * (1.0f / 128.0f) - mB * mB;
        float rsB = rsqrtf(vB + 1e-5f);
#pragma unroll
        for (int nt = 0; nt < 8; nt++) {
            int col = wx * 64 + nt * 8 + 2 * tig;
            float2 gg = *(const float2*)(g2 + col);
            float2 bb = *(const float2*)(b2 + col);
            float2 sA = *(const float2*)(src + (size_t)(r0 + rA) * D + col);
            float2 sB = *(const float2*)(src + (size_t)(r0 + rB) * D + col);
            *(float2*)(out + (size_t)(r0 + rA) * D + col) =
                make_float2((c[mt][nt][0] - mA) * rsA * gg.x + bb.x + sA.x,
                            (c[mt][nt][1] - mA) * rsA * gg.y + bb.y + sA.y);
            *(float2*)(out + (size_t)(r0 + rB) * D + col) =
                make_float2((c[mt][nt][2] - mB) * rsB * gg.x + bb.x + sB.x,
                            (c[mt][nt][3] - mB) * rsB * gg.y + bb.y + sB.y);
        }
    }
}

// ------------------------- launch -------------------------
extern "C" void kernel_launch(void* const* d_in, const int* in_sizes, int n_in,
                              void* d_out, int out_size) {
    (void)in_sizes; (void)n_in; (void)out_size;
    const float* src  = (const float*)d_in[0];
    const float* tgt  = (const float*)d_in[1];
    const float* mask = (const float*)d_in[2];
    const float* Wq   = (const float*)d_in[8];
    const float* Wk   = (const float*)d_in[9];
    const float* Wv   = (const float*)d_in[10];
    const float* Wm   = (const float*)d_in[11];
    const float* g1   = (const float*)d_in[12];
    const float* b1   = (const float*)d_in[13];
    const float* W1   = (const float*)d_in[14];
    const float* W2   = (const float*)d_in[15];
    const float* g2   = (const float*)d_in[16];
    const float* b2   = (const float*)d_in[17];
    float* out = (float*)d_out;

    k_qkv<<<dim3(256, 3), 256>>>(src, tgt, Wq, Wk, Wv);
    cudaFuncSetAttribute(k_attn, cudaFuncAttributeMaxDynamicSharedMemorySize, ATTN_SMEM);
    k_attn<<<dim3(16, 16), 256, ATTN_SMEM>>>(mask);
    k_msg<<<256, 256>>>(Wm, g1, b1);
    k_h<<<dim3(256, 8), 256>>>(src, W1);
    k_out<<<256, 256>>>(src, W2, g2, b2, out);
}

// round 16
// speedup vs baseline: 4.5679x; 1.6241x over previous
#include <cuda_runtime.h>
#include <cuda_fp16.h>
#include <math.h>
#include <stdint.h>

// Problem dims (hardcoded per reference): B=4, H=64, W=128, D=128, NS=2
#define D 128
#define LWIN 2048
#define NWIN 16
#define NTOK 32768

// padded leading dims in 4-byte units (uints of packed half2); all ≡ 4 (mod 32) → conflict-free
#define LA2 68    // K=128 (64 uints + 4 pad)
#define LH2 132   // K=256 (128 + 4)
#define LC2 36    // K=64  (32 + 4)

// ------------------------- scratch (static device memory) -------------------------
__device__ __half g_srch[NTOK * D];                    // src as half
__device__ __half g_tgth[NTOK * D];                    // tgt as half
__device__ __half g_Wh[4][D * D];                      // Wq(pre-scaled)/Wk/Wv/Wm as [n][k] half
__device__ __half g_W1h[1024 * 256];                   // W1^T  [n][k] half
__device__ __half g_W2h[128 * 1024];                   // W2^T  [n][k] half
__device__ __half g_qh[NWIN * LWIN * D];               // windowed q (scale folded in)
__device__ __half g_kh[NWIN * LWIN * D];               // windowed k
__device__ __half g_vTh[NWIN * D * LWIN];              // windowed v transposed [w][d][l]
__device__ float  g_ao[NWIN * LWIN * D];               // attn out fp32 (windowed)
__device__ __half g_msgh[NTOK * D];                    // LN(attn@Wm), original order, half
__device__ __half g_hh[(size_t)NTOK * 1024];           // gelu hidden, half

// ------------------------- index maps (roll + window partition fused) --------------
__device__ __forceinline__ int win_to_src(int w, int l) {
    int b = w >> 2, wi = w & 3;
    int i = wi >> 1, j = wi & 1;
    int y = l >> 6, x = l & 63;            // hh=32, ww=64
    int ys = i * 32 + y, xs = j * 64 + x;
    int yo = (ys + 16) & 63, xo = (xs + 32) & 127;
    return (b << 13) + (yo << 7) + xo;
}
__device__ __forceinline__ int src_to_win(int r) {
    int b = r >> 13, yo = (r >> 7) & 63, xo = r & 127;
    int ym = (yo + 48) & 63, xm = (xo + 96) & 127;
    int i = ym >> 5, y = ym & 31;
    int j = xm >> 6, x = xm & 63;
    int w = (b << 2) + (i << 1) + j;
    int l = (y << 6) + x;
    return w * LWIN + l;
}

// ------------------------- fp16 helpers -------------------------
__device__ __forceinline__ unsigned h2u(float lo, float hi) {
    __half2 h = __floats2half2_rn(lo, hi);
    return *(unsigned*)&h;
}

__device__ __forceinline__ void mmah(float* c, const unsigned* a, const unsigned* b) {
    asm volatile("mma.sync.aligned.m16n8k16.row.col.f32.f16.f16.f32 "
                 "{%0,%1,%2,%3}, {%4,%5,%6,%7}, {%8,%9}, {%0,%1,%2,%3};\n"
                 : "+f"(c[0]), "+f"(c[1]), "+f"(c[2]), "+f"(c[3])
                 : "r"(a[0]), "r"(a[1]), "r"(a[2]), "r"(a[3]), "r"(b[0]), "r"(b[1]));
}

// one K=16 chunk: A natural [m][k-pairs] (lda2 uints/row), B n-major [n][k-pairs]
template <int MT, int NT>
__device__ __forceinline__ void mmah_k16(const unsigned* __restrict__ As, int lda2,
                                         const unsigned* __restrict__ Bs, int ldb2,
                                         float c[MT][NT][4], int mb0, int nb0, int k2,
                                         int g, int tig) {
    unsigned a[MT][4], b[NT][2];
#pragma unroll
    for (int mt = 0; mt < MT; mt++) {
        const unsigned* ap = As + (mb0 + mt * 16 + g) * lda2 + k2 + tig;
        a[mt][0] = ap[0];
        a[mt][1] = ap[8 * lda2];
        a[mt][2] = ap[4];
        a[mt][3] = ap[8 * lda2 + 4];
    }
#pragma unroll
    for (int nt = 0; nt < NT; nt++) {
        const unsigned* bp = Bs + (nb0 + nt * 8 + g) * ldb2 + k2 + tig;
        b[nt][0] = bp[0];
        b[nt][1] = bp[4];
    }
#pragma unroll
    for (int mt = 0; mt < MT; mt++)
#pragma unroll
        for (int nt = 0; nt < NT; nt++) mmah(c[mt][nt], a[mt], b[nt]);
}

// cp.async helpers
__device__ __forceinline__ void cp16(unsigned* s, const void* g) {
    unsigned sa = (unsigned)__cvta_generic_to_shared(s);
    asm volatile("cp.async.cg.shared.global [%0], [%1], 16;" :: "r"(sa), "l"(g));
}
__device__ __forceinline__ void cp_commit() { asm volatile("cp.async.commit_group;"); }
template <int N>
__device__ __forceinline__ void cp_wait() { asm volatile("cp.async.wait_group %0;" :: "n"(N)); }

// ------------------------- K0: one-time conversions -------------------------
__global__ void __launch_bounds__(256) k_prep(const float* __restrict__ src,
                                              const float* __restrict__ tgt,
                                              const float* __restrict__ Wq,
                                              const float* __restrict__ Wk,
                                              const float* __restrict__ Wv,
                                              const float* __restrict__ Wm,
                                              const float* __restrict__ W1,
                                              const float* __restrict__ W2) {
    int sec = blockIdx.y;
    int stride = gridDim.x * blockDim.x;
    int t = blockIdx.x * blockDim.x + threadIdx.x;
    if (sec <= 1) {
        const float* s = sec ? tgt : src;
        unsigned* du = sec ? (unsigned*)g_tgth : (unsigned*)g_srch;
        for (int i = t; i < NTOK * D / 4; i += stride) {
            float4 v = *(const float4*)(s + (size_t)i * 4);
            du[i * 2]     = h2u(v.x, v.y);
            du[i * 2 + 1] = h2u(v.z, v.w);
        }
    } else if (sec == 2) {
        for (int e = t; e < 4 * D * D; e += stride) {
            int w = e >> 14, n = (e >> 7) & 127, k = e & 127;
            const float* W = (w == 0) ? Wq : (w == 1) ? Wk : (w == 2) ? Wv : Wm;
            float v = W[k * D + n];
            if (w == 0) v *= 0.08838834764831845f;   // fold 1/sqrt(128) into Wq
            g_Wh[w][n * D + k] = __float2half_rn(v);
        }
    } else if (sec == 3) {
        for (int e = t; e < 1024 * 256; e += stride) {
            int n = e >> 8, k = e & 255;
            g_W1h[e] = __float2half_rn(W1[k * 1024 + n]);
        }
    } else {
        for (int e = t; e < 128 * 1024; e += stride) {
            int n = e >> 10, k = e & 1023;
            g_W2h[e] = __float2half_rn(W2[k * 128 + n]);
        }
    }
}

// ------------------------- K1: QKV projection (fully smem-resident) -----------------
// dyn smem: As[128][LA2] + Bs[128][LA2] uints = 69632 B
__global__ void __launch_bounds__(256) k_qkv() {
    extern __shared__ unsigned smu[];
    unsigned* As = smu;
    unsigned* Bs = smu + 128 * LA2;
    __shared__ int rowmap[128];
    int tid = threadIdx.x;
    int which = blockIdx.y;              // 0=q, 1=k, 2=v
    int t0 = blockIdx.x * 128;
    if (tid < 128) { int t = t0 + tid; rowmap[tid] = win_to_src(t >> 11, t & 2047); }
    __syncthreads();
    int m = tid >> 1, hf = tid & 1;
    {
        const unsigned* srcu = (const unsigned*)((which == 0) ? g_srch : g_tgth);
        const unsigned* rp = srcu + (size_t)rowmap[m] * 64 + hf * 32;
        unsigned* dA = As + m * LA2 + hf * 32;
        const unsigned* wp = (const unsigned*)g_Wh[which] + m * 64 + hf * 32;
        unsigned* dB = Bs + m * LA2 + hf * 32;
#pragma unroll
        for (int j = 0; j < 8; j++) {
            *(uint4*)(dA + j * 4) = *(const uint4*)(rp + j * 4);
            *(uint4*)(dB + j * 4) = *(const uint4*)(wp + j * 4);
        }
    }
    __syncthreads();
    int warp = tid >> 5, lane = tid & 31, wy = warp >> 1, wx = warp & 1;
    int g = lane >> 2, tig = lane & 3;
    float c[2][8][4] = {};
#pragma unroll
    for (int kc = 0; kc < 8; kc++)
        mmah_k16<2, 8>(As, LA2, Bs, LA2, c, wy * 32, wx * 64, kc * 8, g, tig);

    if (which < 2) {
        unsigned* out = (which == 0) ? (unsigned*)g_qh : (unsigned*)g_kh;
#pragma unroll
        for (int mt = 0; mt < 2; mt++) {
            int r = t0 + wy * 32 + mt * 16 + g;
#pragma unroll
            for (int nt = 0; nt < 8; nt++) {
                int ci = wx * 32 + nt * 4 + tig;   // col/2
                out[(size_t)r * 64 + ci]       = h2u(c[mt][nt][0], c[mt][nt][1]);
                out[(size_t)(r + 8) * 64 + ci] = h2u(c[mt][nt][2], c[mt][nt][3]);
            }
        }
    } else {
        int w = t0 >> 11, l0 = t0 & 2047;
        __half* VT = g_vTh + (size_t)w * D * LWIN;
#pragma unroll
        for (int mt = 0; mt < 2; mt++) {
            int l = l0 + wy * 32 + mt * 16 + g;
#pragma unroll
            for (int nt = 0; nt < 8; nt++) {
                int col = wx * 64 + nt * 8 + 2 * tig;
                VT[(size_t)col * LWIN + l]           = __float2half_rn(c[mt][nt][0]);
                VT[(size_t)(col + 1) * LWIN + l]     = __float2half_rn(c[mt][nt][1]);
                VT[(size_t)col * LWIN + l + 8]       = __float2half_rn(c[mt][nt][2]);
                VT[(size_t)(col + 1) * LWIN + l + 8] = __float2half_rn(c[mt][nt][3]);
            }
        }
    }
}

// ------------------------- K2: flash attention, fp16 + cp.async pipelined -----------
// uint offsets: Qs 128*LA2 | Ks 2*64*LA2 | Vs 128*LC2 | Ps 128*LC2 | smax 256 | ssum 256
#define A_QS 0
#define A_KS (128 * LA2)
#define A_VS (A_KS + 2 * 64 * LA2)
#define A_PS (A_VS + 128 * LC2)
#define A_SMAX (A_PS + 128 * LC2)
#define A_SSUM (A_SMAX + 256)
#define ATTN_SMEM ((A_SSUM + 256) * 4)

__global__ void __launch_bounds__(256, 2) k_attn(const float* __restrict__ mask) {
    extern __shared__ unsigned smu[];
    unsigned* Qs = smu + A_QS;
    unsigned* KsB = smu + A_KS;
    unsigned* Vs = smu + A_VS;
    unsigned* Ps = smu + A_PS;
    float* smax = (float*)(smu + A_SMAX);
    float* ssum = (float*)(smu + A_SSUM);

    int tid = threadIdx.x;
    int m0 = blockIdx.x * 128, w = blockIdx.y;
    const unsigned* Qg = (const unsigned*)g_qh + ((size_t)w * LWIN + m0) * 64;
    const __half* Kwin = g_kh + (size_t)w * LWIN * D;
    const __half* VTwin = g_vTh + (size_t)w * D * LWIN;
    const float* M = mask + (size_t)(w & 3) * LWIN * LWIN;

    int warp = tid >> 5, lane = tid & 31, wy = warp >> 1, wx = warp & 1;
    int g = lane >> 2, tig = lane & 3;

    // stage Q (scale already folded into Wq)
    {
        int m = tid >> 1, hf = tid & 1;
        const unsigned* rp = Qg + (size_t)m * 64 + hf * 32;
        unsigned* dQ = Qs + m * LA2 + hf * 32;
#pragma unroll
        for (int j = 0; j < 8; j++) *(uint4*)(dQ + j * 4) = *(const uint4*)(rp + j * 4);
    }
    // prefetch K(0): 64 rows x 256B
#pragma unroll
    for (int j = 0; j < 4; j++) {
        int e = tid + j * 256, row = e >> 4, seg = e & 15;
        cp16(KsB + row * LA2 + seg * 4, Kwin + (size_t)row * D + seg * 8);
    }
    cp_commit();

    float o_acc[2][8][4] = {};
    float m_run[4] = {-INFINITY, -INFINITY, -INFINITY, -INFINITY};
    float l_run[4] = {0.f, 0.f, 0.f, 0.f};
    int cur = 0;

    for (int kt = 0; kt < 32; kt++) {
        __syncthreads();                 // S0: PV(kt-1) done -> Vs/Ps reusable
        // prefetch V(kt): 128 d-rows x 128B
#pragma unroll
        for (int j = 0; j < 4; j++) {
            int e = tid + j * 256, d2 = e >> 3, seg = e & 7;
            cp16(Vs + d2 * LC2 + seg * 4, VTwin + (size_t)d2 * LWIN + kt * 64 + seg * 8);
        }
        cp_commit();                     // pending {K(kt), V(kt)}
        cp_wait<1>();                    // K(kt) landed
        __syncthreads();                 // S1
        const unsigned* Kc = KsB + cur * (64 * LA2);

        float s_acc[2][4][4] = {};
#pragma unroll
        for (int d0 = 0; d0 < 8; d0++)
            mmah_k16<2, 4>(Qs, LA2, Kc, LA2, s_acc, wy * 32, wx * 32, d0 * 8, g, tig);

        // prefetch K(kt+1) into other buffer
        {
            int ktn = (kt + 1) & 31;
            unsigned* Kn = KsB + (cur ^ 1) * (64 * LA2);
#pragma unroll
            for (int j = 0; j < 4; j++) {
                int e = tid + j * 256, row = e >> 4, seg = e & 15;
                cp16(Kn + row * LA2 + seg * 4, Kwin + ((size_t)ktn * 64 + row) * D + seg * 8);
            }
            cp_commit();                 // pending {V(kt), K(kt+1)}
        }

        // mask add + per-slot tile max
        float tmax[4] = {-INFINITY, -INFINITY, -INFINITY, -INFINITY};
#pragma unroll
        for (int mt = 0; mt < 2; mt++) {
            int rg = m0 + wy * 32 + mt * 16 + g;
#pragma unroll
            for (int nt = 0; nt < 4; nt++) {
                int cg = kt * 64 + wx * 32 + nt * 8 + 2 * tig;
                float2 mk0 = *(const float2*)(M + (size_t)rg * LWIN + cg);
                float2 mk1 = *(const float2*)(M + (size_t)(rg + 8) * LWIN + cg);
                s_acc[mt][nt][0] += mk0.x;
                s_acc[mt][nt][1] += mk0.y;
                s_acc[mt][nt][2] += mk1.x;
                s_acc[mt][nt][3] += mk1.y;
                tmax[mt * 2]     = fmaxf(tmax[mt * 2],     fmaxf(s_acc[mt][nt][0], s_acc[mt][nt][1]));
                tmax[mt * 2 + 1] = fmaxf(tmax[mt * 2 + 1], fmaxf(s_acc[mt][nt][2], s_acc[mt][nt][3]));
            }
        }
#pragma unroll
        for (int s = 0; s < 4; s++) {
            tmax[s] = fmaxf(tmax[s], __shfl_xor_sync(0xffffffffu, tmax[s], 1));
            tmax[s] = fmaxf(tmax[s], __shfl_xor_sync(0xffffffffu, tmax[s], 2));
        }
        if (tig == 0) {
#pragma unroll
            for (int s = 0; s < 4; s++) {
                int r = wy * 32 + (s >> 1) * 16 + g + 8 * (s & 1);
                smax[wx * 128 + r] = tmax[s];
            }
        }
        cp_wait<1>();                    // V(kt) landed
        __syncthreads();                 // S2: smax + Vs visible

        float alpha[4], m_new[4], psum[4];
#pragma unroll
        for (int s = 0; s < 4; s++) {
            int r = wy * 32 + (s >> 1) * 16 + g + 8 * (s & 1);
            float mt_tile = fmaxf(smax[r], smax[128 + r]);
            m_new[s] = fmaxf(m_run[s], mt_tile);
            alpha[s] = __expf(m_run[s] - m_new[s]);
            m_run[s] = m_new[s];
            psum[s] = 0.f;
        }
#pragma unroll
        for (int mt = 0; mt < 2; mt++) {
            int rA = wy * 32 + mt * 16 + g;
#pragma unroll
            for (int nt = 0; nt < 4; nt++) {
                int ci = wx * 16 + nt * 4 + tig;   // packed col/2
                float p0 = __expf(s_acc[mt][nt][0] - m_new[mt * 2]);
                float p1 = __expf(s_acc[mt][nt][1] - m_new[mt * 2]);
                float p2 = __expf(s_acc[mt][nt][2] - m_new[mt * 2 + 1]);
                float p3 = __expf(s_acc[mt][nt][3] - m_new[mt * 2 + 1]);
                psum[mt * 2]     += p0 + p1;
                psum[mt * 2 + 1] += p2 + p3;
                Ps[rA * LC2 + ci]       = h2u(p0, p1);
                Ps[(rA + 8) * LC2 + ci] = h2u(p2, p3);
            }
#pragma unroll
            for (int nt = 0; nt < 8; nt++) {
                o_acc[mt][nt][0] *= alpha[mt * 2];
                o_acc[mt][nt][1] *= alpha[mt * 2];
                o_acc[mt][nt][2] *= alpha[mt * 2 + 1];
                o_acc[mt][nt][3] *= alpha[mt * 2 + 1];
            }
        }
#pragma unroll
        for (int s = 0; s < 4; s++) {
            psum[s] += __shfl_xor_sync(0xffffffffu, psum[s], 1);
            psum[s] += __shfl_xor_sync(0xffffffffu, psum[s], 2);
        }
        if (tig == 0) {
#pragma unroll
            for (int s = 0; s < 4; s++) {
                int r = wy * 32 + (s >> 1) * 16 + g + 8 * (s & 1);
                ssum[wx * 128 + r] = psum[s];
            }
        }
        __syncthreads();                 // S3: Ps + ssum visible
#pragma unroll
        for (int s = 0; s < 4; s++) {
            int r = wy * 32 + (s >> 1) * 16 + g + 8 * (s & 1);
            l_run[s] = l_run[s] * alpha[s] + ssum[r] + ssum[128 + r];
        }
#pragma unroll
        for (int kc = 0; kc < 4; kc++)
            mmah_k16<2, 8>(Ps, LC2, Vs, LC2, o_acc, wy * 32, wx * 64, kc * 8, g, tig);
        cur ^= 1;
    }

    float inv[4];
#pragma unroll
    for (int s = 0; s < 4; s++) inv[s] = 1.0f / l_run[s];
    float* O = g_ao + (size_t)(w * LWIN + m0) * D;
#pragma unroll
    for (int mt = 0; mt < 2; mt++) {
        int rA = wy * 32 + mt * 16 + g;
#pragma unroll
        for (int nt = 0; nt < 8; nt++) {
            int col = wx * 64 + nt * 8 + 2 * tig;
            *(float2*)(O + (size_t)rA * D + col) =
                make_float2(o_acc[mt][nt][0] * inv[mt * 2], o_acc[mt][nt][1] * inv[mt * 2]);
            *(float2*)(O + (size_t)(rA + 8) * D + col) =
                make_float2(o_acc[mt][nt][2] * inv[mt * 2 + 1], o_acc[mt][nt][3] * inv[mt * 2 + 1]);
        }
    }
}

// ------------------------- K3: msg = LN((window-merged O) @ Wm) ----------------------
// dyn smem 69632 B
__global__ void __launch_bounds__(256) k_msg(const float* __restrict__ g1,
                                             const float* __restrict__ b1) {
    extern __shared__ unsigned smu[];
    unsigned* As = smu;
    unsigned* Bs = smu + 128 * LA2;
    __shared__ int rowmap[128];
    __shared__ float red1[2 * 128], red2[2 * 128];
    int tid = threadIdx.x;
    int r0 = blockIdx.x * 128;
    if (tid < 128) rowmap[tid] = src_to_win(r0 + tid);
    __syncthreads();
    int m = tid >> 1, hf = tid & 1;
    {
        const float* rp = g_ao + (size_t)rowmap[m] * D + hf * 64;
        unsigned* dA = As + m * LA2 + hf * 32;
        const unsigned* wp = (const unsigned*)g_Wh[3] + m * 64 + hf * 32;
        unsigned* dB = Bs + m * LA2 + hf * 32;
#pragma unroll
        for (int j = 0; j < 8; j++) {
            float4 a = *(const float4*)(rp + j * 8);
            float4 b = *(const float4*)(rp + j * 8 + 4);
            uint4 pk;
            pk.x = h2u(a.x, a.y); pk.y = h2u(a.z, a.w);
            pk.z = h2u(b.x, b.y); pk.w = h2u(b.z, b.w);
            *(uint4*)(dA + j * 4) = pk;
            *(uint4*)(dB + j * 4) = *(const uint4*)(wp + j * 4);
        }
    }
    __syncthreads();
    int warp = tid >> 5, lane = tid & 31, wy = warp >> 1, wx = warp & 1;
    int g = lane >> 2, tig = lane & 3;
    float c[2][8][4] = {};
#pragma unroll
    for (int kc = 0; kc < 8; kc++)
        mmah_k16<2, 8>(As, LA2, Bs, LA2, c, wy * 32, wx * 64, kc * 8, g, tig);

#pragma unroll
    for (int mt = 0; mt < 2; mt++) {
        float sA1 = 0.f, sA2 = 0.f, sB1 = 0.f, sB2 = 0.f;
#pragma unroll
        for (int nt = 0; nt < 8; nt++) {
            sA1 += c[mt][nt][0] + c[mt][nt][1];
            sA2 += c[mt][nt][0] * c[mt][nt][0] + c[mt][nt][1] * c[mt][nt][1];
            sB1 += c[mt][nt][2] + c[mt][nt][3];
            sB2 += c[mt][nt][2] * c[mt][nt][2] + c[mt][nt][3] * c[mt][nt][3];
        }
#pragma unroll
        for (int o = 1; o < 4; o <<= 1) {
            sA1 += __shfl_xor_sync(0xffffffffu, sA1, o);
            sA2 += __shfl_xor_sync(0xffffffffu, sA2, o);
            sB1 += __shfl_xor_sync(0xffffffffu, sB1, o);
            sB2 += __shfl_xor_sync(0xffffffffu, sB2, o);
        }
        if (tig == 0) {
            int rA = wy * 32 + mt * 16 + g, rB = rA + 8;
            red1[wx * 128 + rA] = sA1; red2[wx * 128 + rA] = sA2;
            red1[wx * 128 + rB] = sB1; red2[wx * 128 + rB] = sB2;
        }
    }
    __syncthreads();
    unsigned* outu = (unsigned*)g_msgh;
#pragma unroll
    for (int mt = 0; mt < 2; mt++) {
        int rA = wy * 32 + mt * 16 + g, rB = rA + 8;
        float mA = (red1[rA] + red1[128 + rA]) * (1.0f / 128.0f);
        float vA = (red2[rA] + red2[128 + rA]) * (1.0f / 128.0f) - mA * mA;
        float rsA = rsqrtf(vA + 1e-5f);
        float mB = (red1[rB] + red1[128 + rB]) * (1.0f / 128.0f);
        float vB = (red2[rB] + red2[128 + rB]) * (1.0f / 128.0f) - mB * mB;
        float rsB = rsqrtf(vB + 1e-5f);
#pragma unroll
        for (int nt = 0; nt < 8; nt++) {
            int col = wx * 64 + nt * 8 + 2 * tig;
            float2 gg = *(const float2*)(g1 + col);
            float2 bb = *(const float2*)(b1 + col);
            int ci = col >> 1;
            outu[(size_t)(r0 + rA) * 64 + ci] =
                h2u((c[mt][nt][0] - mA) * rsA * gg.x + bb.x,
                    (c[mt][nt][1] - mA) * rsA * gg.y + bb.y);
            outu[(size_t)(r0 + rB) * 64 + ci] =
                h2u((c[mt][nt][2] - mB) * rsB * gg.x + bb.x,
                    (c[mt][nt][3] - mB) * rsB * gg.y + bb.y);
        }
    }
}

// ------------------------- K4: h = gelu(concat(src,msg) @ W1), fully resident -------
// dyn smem: 2 * 128 * LH2 * 4 = 135168 B
__global__ void __launch_bounds__(256) k_h() {
    extern __shared__ unsigned smu[];
    unsigned* As = smu;
    unsigned* Bs = smu + 128 * LH2;
    int tid = threadIdx.x;
    int r0 = blockIdx.x * 128;
    int nb = blockIdx.y * 128;
    int m = tid >> 1, hf = tid & 1;
    {
        const unsigned* rp = hf ? ((const unsigned*)g_msgh + (size_t)(r0 + m) * 64)
                                : ((const unsigned*)g_srch + (size_t)(r0 + m) * 64);
        unsigned* dA = As + m * LH2 + hf * 64;
        const unsigned* wp = (const unsigned*)g_W1h + (size_t)(nb + m) * 128 + hf * 64;
        unsigned* dB = Bs + m * LH2 + hf * 64;
#pragma unroll
        for (int j = 0; j < 16; j++) {
            *(uint4*)(dA + j * 4) = *(const uint4*)(rp + j * 4);
            *(uint4*)(dB + j * 4) = *(const uint4*)(wp + j * 4);
        }
    }
    __syncthreads();
    int warp = tid >> 5, lane = tid & 31, wy = warp >> 1, wx = warp & 1;
    int g = lane >> 2, tig = lane & 3;
    float c[2][8][4] = {};
#pragma unroll
    for (int kc = 0; kc < 16; kc++)
        mmah_k16<2, 8>(As, LH2, Bs, LH2, c, wy * 32, wx * 64, kc * 8, g, tig);

    unsigned* hu = (unsigned*)g_hh;
#pragma unroll
    for (int mt = 0; mt < 2; mt++) {
        int r = r0 + wy * 32 + mt * 16 + g;
#pragma unroll
        for (int nt = 0; nt < 8; nt++) {
            int col = nb + wx * 64 + nt * 8 + 2 * tig;
            float o[4];
#pragma unroll
            for (int j = 0; j < 4; j++) {
                float x = c[mt][nt][j];
                o[j] = 0.5f * x * (1.0f + erff(x * 0.70710678118654752f));
            }
            hu[(size_t)r * 512 + (col >> 1)]       = h2u(o[0], o[1]);
            hu[(size_t)(r + 8) * 512 + (col >> 1)] = h2u(o[2], o[3]);
        }
    }
}

// ------------------------- K5: out = src + LN(h @ W2), cp.async pipelined ------------
// dyn smem: 2 buf x (A[128][LC2] + B[128][LC2]) = 73728 B
__global__ void __launch_bounds__(256) k_out(const float* __restrict__ src,
                                             const float* __restrict__ g2,
                                             const float* __restrict__ b2,
                                             float* __restrict__ out) {
    extern __shared__ unsigned smu[];
    unsigned* AsB = smu;                    // 2 x 128*LC2
    unsigned* BsB = smu + 2 * 128 * LC2;    // 2 x 128*LC2
    __shared__ float red1[2 * 128], red2[2 * 128];
    int tid = threadIdx.x;
    int r0 = blockIdx.x * 128;
    int warp = tid >> 5, lane = tid & 31, wy = warp >> 1, wx = warp & 1;
    int g = lane >> 2, tig = lane & 3;

    // prefetch chunk 0
#pragma unroll
    for (int j = 0; j < 4; j++) {
        int e = tid + j * 256, row = e >> 3, seg = e & 7;
        cp16(AsB + row * LC2 + seg * 4, g_hh + (size_t)(r0 + row) * 1024 + seg * 8);
        cp16(BsB + row * LC2 + seg * 4, g_W2h + (size_t)row * 1024 + seg * 8);
    }
    cp_commit();

    float c[2][8][4] = {};
    for (int kc = 0; kc < 16; kc++) {
        int cur = kc & 1;
        if (kc + 1 < 16) {
            int nxt = cur ^ 1;
#pragma unroll
            for (int j = 0; j < 4; j++) {
                int e = tid + j * 256, row = e >> 3, seg = e & 7;
                cp16(AsB + nxt * 128 * LC2 + row * LC2 + seg * 4,
                     g_hh + (size_t)(r0 + row) * 1024 + (kc + 1) * 64 + seg * 8);
                cp16(BsB + nxt * 128 * LC2 + row * LC2 + seg * 4,
                     g_W2h + (size_t)row * 1024 + (kc + 1) * 64 + seg * 8);
            }
            cp_commit();
            cp_wait<1>();
        } else {
            cp_wait<0>();
        }
        __syncthreads();
        const unsigned* As = AsB + cur * 128 * LC2;
        const unsigned* Bs = BsB + cur * 128 * LC2;
#pragma unroll
        for (int q = 0; q < 4; q++)
            mmah_k16<2, 8>(As, LC2, Bs, LC2, c, wy * 32, wx * 64, q * 8, g, tig);
        __syncthreads();
    }

#pragma unroll
    for (int mt = 0; mt < 2; mt++) {
        float sA1 = 0.f, sA2 = 0.f, sB1 = 0.f, sB2 = 0.f;
#pragma unroll
        for (int nt = 0; nt < 8; nt++) {
            sA1 += c[mt][nt][0] + c[mt][nt][1];
            sA2 += c[mt][nt][0] * c[mt][nt][0] + c[mt][nt][1] * c[mt][nt][1];
            sB1 += c[mt][nt][2] + c[mt][nt][3];
            sB2 += c[mt][nt][2] * c[mt][nt][2] + c[mt][nt][3] * c[mt][nt][3];
        }
#pragma unroll
        for (int o = 1; o < 4; o <<= 1) {
            sA1 += __shfl_xor_sync(0xffffffffu, sA1, o);
            sA2 += __shfl_xor_sync(0xffffffffu, sA2, o);
            sB1 += __shfl_xor_sync(0xffffffffu, sB1, o);
            sB2 += __shfl_xor_sync(0xffffffffu, sB2, o);
        }
        if (tig == 0) {
            int rA = wy * 32 + mt * 16 + g, rB = rA + 8;
            red1[wx * 128 + rA] = sA1; red2[wx * 128 + rA] = sA2;
            red1[wx * 128 + rB] = sB1; red2[wx * 128 + rB] = sB2;
        }
    }
    __syncthreads();
#pragma unroll
    for (int mt = 0; mt < 2; mt++) {
        int rA = wy * 32 + mt * 16 + g, rB = rA + 8;
        float mA = (red1[rA] + red1[128 + rA]) * (1.0f / 128.0f);
        float vA = (red2[rA] + red2[128 + rA]) * (1.0f / 128.0f) - mA * mA;
        float rsA = rsqrtf(vA + 1e-5f);
        float mB = (red1[rB] + red1[128 + rB]) * (1.0f / 128.0f);
        float vB = (red2[rB] + red2[128 + rB]) * (1.0f / 128.0f) - mB * mB;
        float rsB = rsqrtf(vB + 1e-5f);
#pragma unroll
        for (int nt = 0; nt < 8; nt++) {
            int col = wx * 64 + nt * 8 + 2 * tig;
            float2 gg = *(const float2*)(g2 + col);
            float2 bb = *(const float2*)(b2 + col);
            float2 sA = *(const float2*)(src + (size_t)(r0 + rA) * D + col);
            float2 sB = *(const float2*)(src + (size_t)(r0 + rB) * D + col);
            *(float2*)(out + (size_t)(r0 + rA) * D + col) =
                make_float2((c[mt][nt][0] - mA) * rsA * gg.x + bb.x + sA.x,
                            (c[mt][nt][1] - mA) * rsA * gg.y + bb.y + sA.y);
            *(float2*)(out + (size_t)(r0 + rB) * D + col) =
                make_float2((c[mt][nt][2] - mB) * rsB * gg.x + bb.x + sB.x,
                            (c[mt][nt][3] - mB) * rsB * gg.y + bb.y + sB.y);
        }
    }
}

// ------------------------- launch -------------------------
extern "C" void kernel_launch(void* const* d_in, const int* in_sizes, int n_in,
                              void* d_out, int out_size) {
    (void)in_sizes; (void)n_in; (void)out_size;
    const float* src  = (const float*)d_in[0];
    const float* tgt  = (const float*)d_in[1];
    const float* mask = (const float*)d_in[2];
    const float* Wq   = (const float*)d_in[8];
    const float* Wk   = (const float*)d_in[9];
    const float* Wv   = (const float*)d_in[10];
    const float* Wm   = (const float*)d_in[11];
    const float* g1   = (const float*)d_in[12];
    const float* b1   = (const float*)d_in[13];
    const float* W1   = (const float*)d_in[14];
    const float* W2   = (const float*)d_in[15];
    const float* g2   = (const float*)d_in[16];
    const float* b2   = (const float*)d_in[17];
    float* out = (float*)d_out;

    const int SM_QKV = 2 * 128 * LA2 * 4;        // 69632
    const int SM_H   = 2 * 128 * LH2 * 4;        // 135168
    const int SM_OUT = 4 * 128 * LC2 * 4;        // 73728
    cudaFuncSetAttribute(k_qkv, cudaFuncAttributeMaxDynamicSharedMemorySize, SM_QKV);
    cudaFuncSetAttribute(k_attn, cudaFuncAttributeMaxDynamicSharedMemorySize, ATTN_SMEM);
    cudaFuncSetAttribute(k_msg, cudaFuncAttributeMaxDynamicSharedMemorySize, SM_QKV);
    cudaFuncSetAttribute(k_h, cudaFuncAttributeMaxDynamicSharedMemorySize, SM_H);
    cudaFuncSetAttribute(k_out, cudaFuncAttributeMaxDynamicSharedMemorySize, SM_OUT);

    k_prep<<<dim3(256, 5), 256>>>(src, tgt, Wq, Wk, Wv, Wm, W1, W2);
    k_qkv<<<dim3(256, 3), 256, SM_QKV>>>();
    k_attn<<<dim3(16, 16), 256, ATTN_SMEM>>>(mask);
    k_msg<<<256, 256, SM_QKV>>>(g1, b1);
    k_h<<<dim3(256, 8), 256, SM_H>>>();
    k_out<<<256, 256, SM_OUT>>>(src, g2, b2, out);
}

// round 17
// speedup vs baseline: 4.5743x; 1.0014x over previous
#include <cuda_runtime.h>
#include <cuda_fp16.h>
#include <math.h>
#include <stdint.h>

// Problem dims (hardcoded per reference): B=4, H=64, W=128, D=128, NS=2
#define D 128
#define LWIN 2048
#define NWIN 16
#define NTOK 32768

// padded leading dims in 4-byte units (uints of packed half2); all ≡ 4 (mod 32) → conflict-free
#define LA2 68    // K=128 (64 uints + 4 pad)
#define LH2 132   // K=256 (128 + 4)
#define LC2 36    // K=64  (32 + 4)

// ------------------------- scratch (static device memory) -------------------------
__device__ __half g_srch[NTOK * D];                    // src as half
__device__ __half g_tgth[NTOK * D];                    // tgt as half
__device__ __half g_Wh[4][D * D];                      // Wq(pre-scaled)/Wk/Wv/Wm as [n][k] half
__device__ __half g_W1h[1024 * 256];                   // W1^T  [n][k] half
__device__ __half g_W2h[128 * 1024];                   // W2^T  [n][k] half
__device__ __half g_qh[NWIN * LWIN * D];               // windowed q (scale folded in)
__device__ __half g_kh[NWIN * LWIN * D];               // windowed k
__device__ __half g_vTh[NWIN * D * LWIN];              // windowed v transposed [w][d][l]
__device__ __half g_aoh[NWIN * LWIN * D];              // attn out (windowed), half
__device__ __half g_msgh[NTOK * D];                    // LN(attn@Wm), original order, half

// ------------------------- index maps (roll + window partition fused) --------------
__device__ __forceinline__ int win_to_src(int w, int l) {
    int b = w >> 2, wi = w & 3;
    int i = wi >> 1, j = wi & 1;
    int y = l >> 6, x = l & 63;            // hh=32, ww=64
    int ys = i * 32 + y, xs = j * 64 + x;
    int yo = (ys + 16) & 63, xo = (xs + 32) & 127;
    return (b << 13) + (yo << 7) + xo;
}
__device__ __forceinline__ int src_to_win(int r) {
    int b = r >> 13, yo = (r >> 7) & 63, xo = r & 127;
    int ym = (yo + 48) & 63, xm = (xo + 96) & 127;
    int i = ym >> 5, y = ym & 31;
    int j = xm >> 6, x = xm & 63;
    int w = (b << 2) + (i << 1) + j;
    int l = (y << 6) + x;
    return w * LWIN + l;
}

// ------------------------- fp16 helpers -------------------------
__device__ __forceinline__ unsigned h2u(float lo, float hi) {
    __half2 h = __floats2half2_rn(lo, hi);
    return *(unsigned*)&h;
}

__device__ __forceinline__ void mmah(float* c, const unsigned* a, const unsigned* b) {
    asm volatile("mma.sync.aligned.m16n8k16.row.col.f32.f16.f16.f32 "
                 "{%0,%1,%2,%3}, {%4,%5,%6,%7}, {%8,%9}, {%0,%1,%2,%3};\n"
                 : "+f"(c[0]), "+f"(c[1]), "+f"(c[2]), "+f"(c[3])
                 : "r"(a[0]), "r"(a[1]), "r"(a[2]), "r"(a[3]), "r"(b[0]), "r"(b[1]));
}

// one K=16 chunk: A natural [m][k-pairs] (lda2 uints/row), B n-major [n][k-pairs]
template <int MT, int NT>
__device__ __forceinline__ void mmah_k16(const unsigned* __restrict__ As, int lda2,
                                         const unsigned* __restrict__ Bs, int ldb2,
                                         float c[MT][NT][4], int mb0, int nb0, int k2,
                                         int g, int tig) {
    unsigned a[MT][4], b[NT][2];
#pragma unroll
    for (int mt = 0; mt < MT; mt++) {
        const unsigned* ap = As + (mb0 + mt * 16 + g) * lda2 + k2 + tig;
        a[mt][0] = ap[0];
        a[mt][1] = ap[8 * lda2];
        a[mt][2] = ap[4];
        a[mt][3] = ap[8 * lda2 + 4];
    }
#pragma unroll
    for (int nt = 0; nt < NT; nt++) {
        const unsigned* bp = Bs + (nb0 + nt * 8 + g) * ldb2 + k2 + tig;
        b[nt][0] = bp[0];
        b[nt][1] = bp[4];
    }
#pragma unroll
    for (int mt = 0; mt < MT; mt++)
#pragma unroll
        for (int nt = 0; nt < NT; nt++) mmah(c[mt][nt], a[mt], b[nt]);
}

// cp.async helpers
__device__ __forceinline__ void cp16(unsigned* s, const void* g) {
    unsigned sa = (unsigned)__cvta_generic_to_shared(s);
    asm volatile("cp.async.cg.shared.global [%0], [%1], 16;" :: "r"(sa), "l"(g));
}
__device__ __forceinline__ void cp_commit() { asm volatile("cp.async.commit_group;"); }
template <int N>
__device__ __forceinline__ void cp_wait() { asm volatile("cp.async.wait_group %0;" :: "n"(N)); }

// ------------------------- K0: one-time conversions -------------------------
__global__ void __launch_bounds__(256) k_prep(const float* __restrict__ src,
                                              const float* __restrict__ tgt,
                                              const float* __restrict__ Wq,
                                              const float* __restrict__ Wk,
                                              const float* __restrict__ Wv,
                                              const float* __restrict__ Wm,
                                              const float* __restrict__ W1,
                                              const float* __restrict__ W2) {
    int sec = blockIdx.y;
    int stride = gridDim.x * blockDim.x;
    int t = blockIdx.x * blockDim.x + threadIdx.x;
    if (sec <= 1) {
        const float* s = sec ? tgt : src;
        unsigned* du = sec ? (unsigned*)g_tgth : (unsigned*)g_srch;
        for (int i = t; i < NTOK * D / 4; i += stride) {
            float4 v = *(const float4*)(s + (size_t)i * 4);
            du[i * 2]     = h2u(v.x, v.y);
            du[i * 2 + 1] = h2u(v.z, v.w);
        }
    } else if (sec == 2) {
        for (int e = t; e < 4 * D * D; e += stride) {
            int w = e >> 14, n = (e >> 7) & 127, k = e & 127;
            const float* W = (w == 0) ? Wq : (w == 1) ? Wk : (w == 2) ? Wv : Wm;
            float v = W[k * D + n];
            if (w == 0) v *= 0.08838834764831845f;   // fold 1/sqrt(128) into Wq
            g_Wh[w][n * D + k] = __float2half_rn(v);
        }
    } else if (sec == 3) {
        for (int e = t; e < 1024 * 256; e += stride) {
            int n = e >> 8, k = e & 255;
            g_W1h[e] = __float2half_rn(W1[k * 1024 + n]);
        }
    } else {
        for (int e = t; e < 128 * 1024; e += stride) {
            int n = e >> 10, k = e & 1023;
            g_W2h[e] = __float2half_rn(W2[k * 128 + n]);
        }
    }
}

// ------------------------- K1: fused QKV projection (A tiles staged once) -----------
// dyn smem: As_src + As_tgt + Bs = 3 * 128 * LA2 uints = 104448 B
__global__ void __launch_bounds__(256) k_qkv() {
    extern __shared__ unsigned smu[];
    unsigned* As0 = smu;                      // src rows (gathered)
    unsigned* As1 = smu + 128 * LA2;          // tgt rows (gathered)
    unsigned* Bs  = smu + 2 * 128 * LA2;      // weight tile
    __shared__ int rowmap[128];
    int tid = threadIdx.x;
    int t0 = blockIdx.x * 128;
    if (tid < 128) { int t = t0 + tid; rowmap[tid] = win_to_src(t >> 11, t & 2047); }
    __syncthreads();
    int m = tid >> 1, hf = tid & 1;
    {
        const unsigned* rp0 = (const unsigned*)g_srch + (size_t)rowmap[m] * 64 + hf * 32;
        const unsigned* rp1 = (const unsigned*)g_tgth + (size_t)rowmap[m] * 64 + hf * 32;
        unsigned* d0 = As0 + m * LA2 + hf * 32;
        unsigned* d1 = As1 + m * LA2 + hf * 32;
#pragma unroll
        for (int j = 0; j < 8; j++) {
            *(uint4*)(d0 + j * 4) = *(const uint4*)(rp0 + j * 4);
            *(uint4*)(d1 + j * 4) = *(const uint4*)(rp1 + j * 4);
        }
    }
    int warp = tid >> 5, lane = tid & 31, wy = warp >> 1, wx = warp & 1;
    int g = lane >> 2, tig = lane & 3;

    for (int which = 0; which < 3; which++) {
        // stage weight tile (readers of previous Bs finished at loop-end sync)
        {
            const unsigned* wp = (const unsigned*)g_Wh[which] + m * 64 + hf * 32;
            unsigned* dB = Bs + m * LA2 + hf * 32;
#pragma unroll
            for (int j = 0; j < 8; j++) *(uint4*)(dB + j * 4) = *(const uint4*)(wp + j * 4);
        }
        __syncthreads();
        const unsigned* As = (which == 0) ? As0 : As1;
        float c[2][8][4] = {};
#pragma unroll
        for (int kc = 0; kc < 8; kc++)
            mmah_k16<2, 8>(As, LA2, Bs, LA2, c, wy * 32, wx * 64, kc * 8, g, tig);

        if (which < 2) {
            unsigned* out = (which == 0) ? (unsigned*)g_qh : (unsigned*)g_kh;
#pragma unroll
            for (int mt = 0; mt < 2; mt++) {
                int r = t0 + wy * 32 + mt * 16 + g;
#pragma unroll
                for (int nt = 0; nt < 8; nt++) {
                    int ci = wx * 32 + nt * 4 + tig;   // col/2
                    out[(size_t)r * 64 + ci]       = h2u(c[mt][nt][0], c[mt][nt][1]);
                    out[(size_t)(r + 8) * 64 + ci] = h2u(c[mt][nt][2], c[mt][nt][3]);
                }
            }
        } else {
            int w = t0 >> 11, l0 = t0 & 2047;
            __half* VT = g_vTh + (size_t)w * D * LWIN;
#pragma unroll
            for (int mt = 0; mt < 2; mt++) {
                int l = l0 + wy * 32 + mt * 16 + g;
#pragma unroll
                for (int nt = 0; nt < 8; nt++) {
                    int col = wx * 64 + nt * 8 + 2 * tig;
                    VT[(size_t)col * LWIN + l]           = __float2half_rn(c[mt][nt][0]);
                    VT[(size_t)(col + 1) * LWIN + l]     = __float2half_rn(c[mt][nt][1]);
                    VT[(size_t)col * LWIN + l + 8]       = __float2half_rn(c[mt][nt][2]);
                    VT[(size_t)(col + 1) * LWIN + l + 8] = __float2half_rn(c[mt][nt][3]);
                }
            }
        }
        __syncthreads();   // Bs reads complete before restage
    }
}

// ------------------------- K2: flash attention, fp16 + cp.async pipelined -----------
// uint offsets: Qs 128*LA2 | Ks 2*64*LA2 | Vs 128*LC2 | Ps 128*LC2 | smax 256 | ssum 256
#define A_QS 0
#define A_KS (128 * LA2)
#define A_VS (A_KS + 2 * 64 * LA2)
#define A_PS (A_VS + 128 * LC2)
#define A_SMAX (A_PS + 128 * LC2)
#define A_SSUM (A_SMAX + 256)
#define ATTN_SMEM ((A_SSUM + 256) * 4)

__global__ void __launch_bounds__(256, 2) k_attn(const float* __restrict__ mask) {
    extern __shared__ unsigned smu[];
    unsigned* Qs = smu + A_QS;
    unsigned* KsB = smu + A_KS;
    unsigned* Vs = smu + A_VS;
    unsigned* Ps = smu + A_PS;
    float* smax = (float*)(smu + A_SMAX);
    float* ssum = (float*)(smu + A_SSUM);

    int tid = threadIdx.x;
    int m0 = blockIdx.x * 128, w = blockIdx.y;
    const unsigned* Qg = (const unsigned*)g_qh + ((size_t)w * LWIN + m0) * 64;
    const __half* Kwin = g_kh + (size_t)w * LWIN * D;
    const __half* VTwin = g_vTh + (size_t)w * D * LWIN;
    const float* M = mask + (size_t)(w & 3) * LWIN * LWIN;

    int warp = tid >> 5, lane = tid & 31, wy = warp >> 1, wx = warp & 1;
    int g = lane >> 2, tig = lane & 3;

    // stage Q (scale already folded into Wq)
    {
        int m = tid >> 1, hf = tid & 1;
        const unsigned* rp = Qg + (size_t)m * 64 + hf * 32;
        unsigned* dQ = Qs + m * LA2 + hf * 32;
#pragma unroll
        for (int j = 0; j < 8; j++) *(uint4*)(dQ + j * 4) = *(const uint4*)(rp + j * 4);
    }
    // prefetch K(0): 64 rows x 256B
#pragma unroll
    for (int j = 0; j < 4; j++) {
        int e = tid + j * 256, row = e >> 4, seg = e & 15;
        cp16(KsB + row * LA2 + seg * 4, Kwin + (size_t)row * D + seg * 8);
    }
    cp_commit();

    float o_acc[2][8][4] = {};
    float m_run[4] = {-INFINITY, -INFINITY, -INFINITY, -INFINITY};
    float l_run[4] = {0.f, 0.f, 0.f, 0.f};
    int cur = 0;

    for (int kt = 0; kt < 32; kt++) {
        __syncthreads();                 // S0: PV(kt-1) done -> Vs/Ps reusable
        // prefetch V(kt): 128 d-rows x 128B
#pragma unroll
        for (int j = 0; j < 4; j++) {
            int e = tid + j * 256, d2 = e >> 3, seg = e & 7;
            cp16(Vs + d2 * LC2 + seg * 4, VTwin + (size_t)d2 * LWIN + kt * 64 + seg * 8);
        }
        cp_commit();                     // pending {K(kt), V(kt)}
        cp_wait<1>();                    // K(kt) landed
        __syncthreads();                 // S1
        const unsigned* Kc = KsB + cur * (64 * LA2);

        float s_acc[2][4][4] = {};
#pragma unroll
        for (int d0 = 0; d0 < 8; d0++)
            mmah_k16<2, 4>(Qs, LA2, Kc, LA2, s_acc, wy * 32, wx * 32, d0 * 8, g, tig);

        // prefetch K(kt+1) into other buffer
        {
            int ktn = (kt + 1) & 31;
            unsigned* Kn = KsB + (cur ^ 1) * (64 * LA2);
#pragma unroll
            for (int j = 0; j < 4; j++) {
                int e = tid + j * 256, row = e >> 4, seg = e & 15;
                cp16(Kn + row * LA2 + seg * 4, Kwin + ((size_t)ktn * 64 + row) * D + seg * 8);
            }
            cp_commit();                 // pending {V(kt), K(kt+1)}
        }

        // mask add + per-slot tile max
        float tmax[4] = {-INFINITY, -INFINITY, -INFINITY, -INFINITY};
#pragma unroll
        for (int mt = 0; mt < 2; mt++) {
            int rg = m0 + wy * 32 + mt * 16 + g;
#pragma unroll
            for (int nt = 0; nt < 4; nt++) {
                int cg = kt * 64 + wx * 32 + nt * 8 + 2 * tig;
                float2 mk0 = *(const float2*)(M + (size_t)rg * LWIN + cg);
                float2 mk1 = *(const float2*)(M + (size_t)(rg + 8) * LWIN + cg);
                s_acc[mt][nt][0] += mk0.x;
                s_acc[mt][nt][1] += mk0.y;
                s_acc[mt][nt][2] += mk1.x;
                s_acc[mt][nt][3] += mk1.y;
                tmax[mt * 2]     = fmaxf(tmax[mt * 2],     fmaxf(s_acc[mt][nt][0], s_acc[mt][nt][1]));
                tmax[mt * 2 + 1] = fmaxf(tmax[mt * 2 + 1], fmaxf(s_acc[mt][nt][2], s_acc[mt][nt][3]));
            }
        }
#pragma unroll
        for (int s = 0; s < 4; s++) {
            tmax[s] = fmaxf(tmax[s], __shfl_xor_sync(0xffffffffu, tmax[s], 1));
            tmax[s] = fmaxf(tmax[s], __shfl_xor_sync(0xffffffffu, tmax[s], 2));
        }
        if (tig == 0) {
#pragma unroll
            for (int s = 0; s < 4; s++) {
                int r = wy * 32 + (s >> 1) * 16 + g + 8 * (s & 1);
                smax[wx * 128 + r] = tmax[s];
            }
        }
        cp_wait<1>();                    // V(kt) landed
        __syncthreads();                 // S2: smax + Vs visible

        float alpha[4], m_new[4], psum[4];
#pragma unroll
        for (int s = 0; s < 4; s++) {
            int r = wy * 32 + (s >> 1) * 16 + g + 8 * (s & 1);
            float mt_tile = fmaxf(smax[r], smax[128 + r]);
            m_new[s] = fmaxf(m_run[s], mt_tile);
            alpha[s] = __expf(m_run[s] - m_new[s]);
            m_run[s] = m_new[s];
            psum[s] = 0.f;
        }
#pragma unroll
        for (int mt = 0; mt < 2; mt++) {
            int rA = wy * 32 + mt * 16 + g;
#pragma unroll
            for (int nt = 0; nt < 4; nt++) {
                int ci = wx * 16 + nt * 4 + tig;   // packed col/2
                float p0 = __expf(s_acc[mt][nt][0] - m_new[mt * 2]);
                float p1 = __expf(s_acc[mt][nt][1] - m_new[mt * 2]);
                float p2 = __expf(s_acc[mt][nt][2] - m_new[mt * 2 + 1]);
                float p3 = __expf(s_acc[mt][nt][3] - m_new[mt * 2 + 1]);
                psum[mt * 2]     += p0 + p1;
                psum[mt * 2 + 1] += p2 + p3;
                Ps[rA * LC2 + ci]       = h2u(p0, p1);
                Ps[(rA + 8) * LC2 + ci] = h2u(p2, p3);
            }
#pragma unroll
            for (int nt = 0; nt < 8; nt++) {
                o_acc[mt][nt][0] *= alpha[mt * 2];
                o_acc[mt][nt][1] *= alpha[mt * 2];
                o_acc[mt][nt][2] *= alpha[mt * 2 + 1];
                o_acc[mt][nt][3] *= alpha[mt * 2 + 1];
            }
        }
#pragma unroll
        for (int s = 0; s < 4; s++) {
            psum[s] += __shfl_xor_sync(0xffffffffu, psum[s], 1);
            psum[s] += __shfl_xor_sync(0xffffffffu, psum[s], 2);
        }
        if (tig == 0) {
#pragma unroll
            for (int s = 0; s < 4; s++) {
                int r = wy * 32 + (s >> 1) * 16 + g + 8 * (s & 1);
                ssum[wx * 128 + r] = psum[s];
            }
        }
        __syncthreads();                 // S3: Ps + ssum visible
#pragma unroll
        for (int s = 0; s < 4; s++) {
            int r = wy * 32 + (s >> 1) * 16 + g + 8 * (s & 1);
            l_run[s] = l_run[s] * alpha[s] + ssum[r] + ssum[128 + r];
        }
#pragma unroll
        for (int kc = 0; kc < 4; kc++)
            mmah_k16<2, 8>(Ps, LC2, Vs, LC2, o_acc, wy * 32, wx * 64, kc * 8, g, tig);
        cur ^= 1;
    }

    float inv[4];
#pragma unroll
    for (int s = 0; s < 4; s++) inv[s] = 1.0f / l_run[s];
    unsigned* O = (unsigned*)g_aoh + ((size_t)w * LWIN + m0) * 64;
#pragma unroll
    for (int mt = 0; mt < 2; mt++) {
        int rA = wy * 32 + mt * 16 + g;
#pragma unroll
        for (int nt = 0; nt < 8; nt++) {
            int ci = wx * 32 + nt * 4 + tig;   // col/2
            O[(size_t)rA * 64 + ci] =
                h2u(o_acc[mt][nt][0] * inv[mt * 2], o_acc[mt][nt][1] * inv[mt * 2]);
            O[(size_t)(rA + 8) * 64 + ci] =
                h2u(o_acc[mt][nt][2] * inv[mt * 2 + 1], o_acc[mt][nt][3] * inv[mt * 2 + 1]);
        }
    }
}

// ------------------------- K3: msg = LN((window-merged O) @ Wm) ----------------------
// dyn smem 69632 B
__global__ void __launch_bounds__(256) k_msg(const float* __restrict__ g1,
                                             const float* __restrict__ b1) {
    extern __shared__ unsigned smu[];
    unsigned* As = smu;
    unsigned* Bs = smu + 128 * LA2;
    __shared__ int rowmap[128];
    __shared__ float red1[2 * 128], red2[2 * 128];
    int tid = threadIdx.x;
    int r0 = blockIdx.x * 128;
    if (tid < 128) rowmap[tid] = src_to_win(r0 + tid);
    __syncthreads();
    int m = tid >> 1, hf = tid & 1;
    {
        const unsigned* rp = (const unsigned*)g_aoh + (size_t)rowmap[m] * 64 + hf * 32;
        unsigned* dA = As + m * LA2 + hf * 32;
        const unsigned* wp = (const unsigned*)g_Wh[3] + m * 64 + hf * 32;
        unsigned* dB = Bs + m * LA2 + hf * 32;
#pragma unroll
        for (int j = 0; j < 8; j++) {
            *(uint4*)(dA + j * 4) = *(const uint4*)(rp + j * 4);
            *(uint4*)(dB + j * 4) = *(const uint4*)(wp + j * 4);
        }
    }
    __syncthreads();
    int warp = tid >> 5, lane = tid & 31, wy = warp >> 1, wx = warp & 1;
    int g = lane >> 2, tig = lane & 3;
    float c[2][8][4] = {};
#pragma unroll
    for (int kc = 0; kc < 8; kc++)
        mmah_k16<2, 8>(As, LA2, Bs, LA2, c, wy * 32, wx * 64, kc * 8, g, tig);

#pragma unroll
    for (int mt = 0; mt < 2; mt++) {
        float sA1 = 0.f, sA2 = 0.f, sB1 = 0.f, sB2 = 0.f;
#pragma unroll
        for (int nt = 0; nt < 8; nt++) {
            sA1 += c[mt][nt][0] + c[mt][nt][1];
            sA2 += c[mt][nt][0] * c[mt][nt][0] + c[mt][nt][1] * c[mt][nt][1];
            sB1 += c[mt][nt][2] + c[mt][nt][3];
            sB2 += c[mt][nt][2] * c[mt][nt][2] + c[mt][nt][3] * c[mt][nt][3];
        }
#pragma unroll
        for (int o = 1; o < 4; o <<= 1) {
            sA1 += __shfl_xor_sync(0xffffffffu, sA1, o);
            sA2 += __shfl_xor_sync(0xffffffffu, sA2, o);
            sB1 += __shfl_xor_sync(0xffffffffu, sB1, o);
            sB2 += __shfl_xor_sync(0xffffffffu, sB2, o);
        }
        if (tig == 0) {
            int rA = wy * 32 + mt * 16 + g, rB = rA + 8;
            red1[wx * 128 + rA] = sA1; red2[wx * 128 + rA] = sA2;
            red1[wx * 128 + rB] = sB1; red2[wx * 128 + rB] = sB2;
        }
    }
    __syncthreads();
    unsigned* outu = (unsigned*)g_msgh;
#pragma unroll
    for (int mt = 0; mt < 2; mt++) {
        int rA = wy * 32 + mt * 16 + g, rB = rA + 8;
        float mA = (red1[rA] + red1[128 + rA]) * (1.0f / 128.0f);
        float vA = (red2[rA] + red2[128 + rA]) * (1.0f / 128.0f) - mA * mA;
        float rsA = rsqrtf(vA + 1e-5f);
        float mB = (red1[rB] + red1[128 + rB]) * (1.0f / 128.0f);
        float vB = (red2[rB] + red2[128 + rB]) * (1.0f / 128.0f) - mB * mB;
        float rsB = rsqrtf(vB + 1e-5f);
#pragma unroll
        for (int nt = 0; nt < 8; nt++) {
            int col = wx * 64 + nt * 8 + 2 * tig;
            float2 gg = *(const float2*)(g1 + col);
            float2 bb = *(const float2*)(b1 + col);
            int ci = col >> 1;
            outu[(size_t)(r0 + rA) * 64 + ci] =
                h2u((c[mt][nt][0] - mA) * rsA * gg.x + bb.x,
                    (c[mt][nt][1] - mA) * rsA * gg.y + bb.y);
            outu[(size_t)(r0 + rB) * 64 + ci] =
                h2u((c[mt][nt][2] - mB) * rsB * gg.x + bb.x,
                    (c[mt][nt][3] - mB) * rsB * gg.y + bb.y);
        }
    }
}

// ------------------------- K4: fused MLP: out = src + LN(gelu(concat@W1)@W2) --------
// dyn smem (uints): Asr 128*LH2 | Bs 128*LH2 | Hs 128*LA2 | Ws 128*LA2 = 51200 -> 204800 B
#define MLP_ASR 0
#define MLP_BS (128 * LH2)
#define MLP_HS (2 * 128 * LH2)
#define MLP_WS (2 * 128 * LH2 + 128 * LA2)
#define MLP_SMEM ((2 * 128 * LH2 + 2 * 128 * LA2) * 4)

__global__ void __launch_bounds__(256, 1) k_mlp(const float* __restrict__ src,
                                                const float* __restrict__ g2,
                                                const float* __restrict__ b2,
                                                float* __restrict__ out) {
    extern __shared__ unsigned smu[];
    unsigned* Asr = smu + MLP_ASR;
    unsigned* Bs = smu + MLP_BS;
    unsigned* Hs = smu + MLP_HS;
    unsigned* Ws = smu + MLP_WS;
    __shared__ float red1[2 * 128], red2[2 * 128];
    int tid = threadIdx.x;
    int r0 = blockIdx.x * 128;
    int m = tid >> 1, hf = tid & 1;
    int warp = tid >> 5, lane = tid & 31, wy = warp >> 1, wx = warp & 1;
    int g = lane >> 2, tig = lane & 3;

    // stage concat(src,msg) rows once: [128][LH2]
    {
        const unsigned* rp = hf ? ((const unsigned*)g_msgh + (size_t)(r0 + m) * 64)
                                : ((const unsigned*)g_srch + (size_t)(r0 + m) * 64);
        unsigned* dA = Asr + m * LH2 + hf * 64;
#pragma unroll
        for (int j = 0; j < 16; j++) *(uint4*)(dA + j * 4) = *(const uint4*)(rp + j * 4);
    }

    float acc2[2][8][4] = {};
    for (int ch = 0; ch < 8; ch++) {
        // stage W1 chunk [n=128][k=256] and W2 chunk [n=128][k=128]
        {
            const unsigned* wp = (const unsigned*)g_W1h + (size_t)(ch * 128 + m) * 128 + hf * 64;
            unsigned* dB = Bs + m * LH2 + hf * 64;
#pragma unroll
            for (int j = 0; j < 16; j++) *(uint4*)(dB + j * 4) = *(const uint4*)(wp + j * 4);
            const unsigned* w2p = (const unsigned*)g_W2h + (size_t)m * 512 + ch * 64 + hf * 32;
            unsigned* dW = Ws + m * LA2 + hf * 32;
#pragma unroll
            for (int j = 0; j < 8; j++) *(uint4*)(dW + j * 4) = *(const uint4*)(w2p + j * 4);
        }
        __syncthreads();   // Asr (first iter), Bs, Ws ready; prev Hs reads done

        float acc1[2][8][4] = {};
#pragma unroll
        for (int kc = 0; kc < 16; kc++)
            mmah_k16<2, 8>(Asr, LH2, Bs, LH2, acc1, wy * 32, wx * 64, kc * 8, g, tig);

        // gelu -> Hs (half packed)
#pragma unroll
        for (int mt = 0; mt < 2; mt++) {
            int rA = wy * 32 + mt * 16 + g;
#pragma unroll
            for (int nt = 0; nt < 8; nt++) {
                int ci = wx * 32 + nt * 4 + tig;
                float o[4];
#pragma unroll
                for (int j = 0; j < 4; j++) {
                    float x = acc1[mt][nt][j];
                    o[j] = 0.5f * x * (1.0f + erff(x * 0.70710678118654752f));
                }
                Hs[rA * LA2 + ci]       = h2u(o[0], o[1]);
                Hs[(rA + 8) * LA2 + ci] = h2u(o[2], o[3]);
            }
        }
        __syncthreads();   // Hs visible to all warps; Bs/Ws reads of this iter done after next mma

        // acc2 += Hs @ W2chunk  (K=128)
#pragma unroll
        for (int kc = 0; kc < 8; kc++)
            mmah_k16<2, 8>(Hs, LA2, Ws, LA2, acc2, wy * 32, wx * 64, kc * 8, g, tig);
        __syncthreads();   // all reads done before restaging Bs/Ws/Hs
    }

    // LN + residual epilogue
#pragma unroll
    for (int mt = 0; mt < 2; mt++) {
        float sA1 = 0.f, sA2 = 0.f, sB1 = 0.f, sB2 = 0.f;
#pragma unroll
        for (int nt = 0; nt < 8; nt++) {
            sA1 += acc2[mt][nt][0] + acc2[mt][nt][1];
            sA2 += acc2[mt][nt][0] * acc2[mt][nt][0] + acc2[mt][nt][1] * acc2[mt][nt][1];
            sB1 += acc2[mt][nt][2] + acc2[mt][nt][3];
            sB2 += acc2[mt][nt][2] * acc2[mt][nt][2] + acc2[mt][nt][3] * acc2[mt][nt][3];
        }
#pragma unroll
        for (int o = 1; o < 4; o <<= 1) {
            sA1 += __shfl_xor_sync(0xffffffffu, sA1, o);
            sA2 += __shfl_xor_sync(0xffffffffu, sA2, o);
            sB1 += __shfl_xor_sync(0xffffffffu, sB1, o);
            sB2 += __shfl_xor_sync(0xffffffffu, sB2, o);
        }
        if (tig == 0) {
            int rA = wy * 32 + mt * 16 + g, rB = rA + 8;
            red1[wx * 128 + rA] = sA1; red2[wx * 128 + rA] = sA2;
            red1[wx * 128 + rB] = sB1; red2[wx * 128 + rB] = sB2;
        }
    }
    __syncthreads();
#pragma unroll
    for (int mt = 0; mt < 2; mt++) {
        int rA = wy * 32 + mt * 16 + g, rB = rA + 8;
        float mA = (red1[rA] + red1[128 + rA]) * (1.0f / 128.0f);
        float vA = (red2[rA] + red2[128 + rA]) * (1.0f / 128.0f) - mA * mA;
        float rsA = rsqrtf(vA + 1e-5f);
        float mB = (red1[rB] + red1[128 + rB]) * (1.0f / 128.0f);
        float vB = (red2[rB] + red2[128 + rB]) * (1.0f / 128.0f) - mB * mB;
        float rsB = rsqrtf(vB + 1e-5f);
#pragma unroll
        for (int nt = 0; nt < 8; nt++) {
            int col = wx * 64 + nt * 8 + 2 * tig;
            float2 gg = *(const float2*)(g2 + col);
            float2 bb = *(const float2*)(b2 + col);
            float2 sA = *(const float2*)(src + (size_t)(r0 + rA) * D + col);
            float2 sB = *(const float2*)(src + (size_t)(r0 + rB) * D + col);
            *(float2*)(out + (size_t)(r0 + rA) * D + col) =
                make_float2((acc2[mt][nt][0] - mA) * rsA * gg.x + bb.x + sA.x,
                            (acc2[mt][nt][1] - mA) * rsA * gg.y + bb.y + sA.y);
            *(float2*)(out + (size_t)(r0 + rB) * D + col) =
                make_float2((acc2[mt][nt][2] - mB) * rsB * gg.x + bb.x + sB.x,
                            (acc2[mt][nt][3] - mB) * rsB * gg.y + bb.y + sB.y);
        }
    }
}

// ------------------------- launch -------------------------
extern "C" void kernel_launch(void* const* d_in, const int* in_sizes, int n_in,
                              void* d_out, int out_size) {
    (void)in_sizes; (void)n_in; (void)out_size;
    const float* src  = (const float*)d_in[0];
    const float* tgt  = (const float*)d_in[1];
    const float* mask = (const float*)d_in[2];
    const float* Wq   = (const float*)d_in[8];
    const float* Wk   = (const float*)d_in[9];
    const float* Wv   = (const float*)d_in[10];
    const float* Wm   = (const float*)d_in[11];
    const float* g1   = (const float*)d_in[12];
    const float* b1   = (const float*)d_in[13];
    const float* W1   = (const float*)d_in[14];
    const float* W2   = (const float*)d_in[15];
    const float* g2   = (const float*)d_in[16];
    const float* b2   = (const float*)d_in[17];
    float* out = (float*)d_out;

    const int SM_QKV = 3 * 128 * LA2 * 4;        // 104448
    const int SM_MSG = 2 * 128 * LA2 * 4;        // 69632
    cudaFuncSetAttribute(k_qkv, cudaFuncAttributeMaxDynamicSharedMemorySize, SM_QKV);
    cudaFuncSetAttribute(k_attn, cudaFuncAttributeMaxDynamicSharedMemorySize, ATTN_SMEM);
    cudaFuncSetAttribute(k_msg, cudaFuncAttributeMaxDynamicSharedMemorySize, SM_MSG);
    cudaFuncSetAttribute(k_mlp, cudaFuncAttributeMaxDynamicSharedMemorySize, MLP_SMEM);

    k_prep<<<dim3(256, 5), 256>>>(src, tgt, Wq, Wk, Wv, Wm, W1, W2);
    k_qkv<<<256, 256, SM_QKV>>>();
    k_attn<<<dim3(16, 16), 256, ATTN_SMEM>>>(mask);
    k_msg<<<256, 256, SM_MSG>>>(g1, b1);
    k_mlp<<<256, 256, MLP_SMEM>>>(src, g2, b2, out);
}